// round 2
// baseline (speedup 1.0000x reference)
#include <cuda_runtime.h>
#include <math.h>

#define D 128
#define NMAX 210048
#define SA 130   // even smem stride -> 8B-aligned float2 rows for LDS.64

// Scratch: Q, K, V, attention-out  (4 * NMAX * 128 floats ~ 430 MB, static)
__device__ float g_scr[(size_t)4 * NMAX * D];
__device__ int g_ws16[20002];
__device__ int g_ws64[8002];

typedef unsigned long long ull;

__device__ __forceinline__ ull pack_dup(float a) {
    ull r;
    asm("mov.b64 %0, {%1, %1};" : "=l"(r) : "f"(a));
    return r;
}
__device__ __forceinline__ void ffma2(ull& acc, ull a, ull b) {
    asm("fma.rn.f32x2 %0, %1, %2, %0;" : "+l"(acc) : "l"(a), "l"(b));
}
__device__ __forceinline__ float2 unpack2(ull v) {
    float2 r;
    asm("mov.b64 {%0, %1}, %2;" : "=f"(r.x), "=f"(r.y) : "l"(v));
    return r;
}

// ---------------------------------------------------------------------------
// Window-start builder (flat_pos strictly increasing -> contiguous ranges).
// ---------------------------------------------------------------------------
__global__ void build_ws(const int* __restrict__ fp, int n, int L,
                         int* __restrict__ ws, int nw)
{
    int i = blockIdx.x * blockDim.x + threadIdx.x;
    if (i < n) {
        int w = fp[i] / L;
        if (i == 0 || fp[i - 1] / L != w) ws[w] = i;
    }
    if (i == 0) ws[nw] = n;
}

// ---------------------------------------------------------------------------
// Tiled GEMM with packed f32x2 FMA.
//   64 tokens x 128 channels per block, K = 128, NM weight matrices per block
//   (NM=2 fuses Q+K: A tile loaded/gathered once).
//   As: 64 x SA,  Bs: 128 x SA with Bs[k*SA + c] = W[c*128 + k].
//   Thread (tx,ty): 4 tokens x 4 channel-PAIRS, channels {2tx, 2tx+1} + 32*v.
//   B operand: direct LDS.64 into b64 reg (no packing). A: mov.b64 {a,a}.
// ---------------------------------------------------------------------------
template <bool ADD_POS, int NM>
__global__ __launch_bounds__(256)
void gemm_tok(const float* __restrict__ X, const int* __restrict__ gidx,
              const float* __restrict__ POS, const int* __restrict__ fp,
              const float* __restrict__ W, const float* __restrict__ bias,
              float* __restrict__ OUT0, float* __restrict__ OUT1,
              const int* __restrict__ sidx, int ntok)
{
    extern __shared__ float sm[];
    float* As = sm;              // 64 x SA
    float* Bs = sm + 64 * SA;    // 128 x SA (k-major)
    const int tid = threadIdx.x;
    const int tb = blockIdx.x * 64;

    // Load A tile (gather + optional pos add), zero-pad tail tokens
#pragma unroll
    for (int it = 0; it < 8; it++) {
        int idx = tid + it * 256;          // 0..2047
        int r  = idx >> 5;                 // 0..63
        int c4 = (idx & 31) << 2;
        int t  = tb + r;
        float4 v = make_float4(0.f, 0.f, 0.f, 0.f);
        if (t < ntok) {
            int src = gidx ? gidx[t] : t;
            v = *(const float4*)(X + (size_t)src * D + c4);
            if (ADD_POS) {
                float4 p = *(const float4*)(POS + (size_t)fp[t] * D + c4);
                v.x += p.x; v.y += p.y; v.z += p.z; v.w += p.w;
            }
        }
        As[r * SA + c4 + 0] = v.x;
        As[r * SA + c4 + 1] = v.y;
        As[r * SA + c4 + 2] = v.z;
        As[r * SA + c4 + 3] = v.w;
    }

    const int tx = tid & 15;
    const int ty = tid >> 4;
    const float* Ap = As + ty * 4 * SA;

#pragma unroll
    for (int m = 0; m < NM; m++) {
        // Load W_m tile, transposed into k-major
        const float* Wm = W + (size_t)m * D * D;
#pragma unroll
        for (int it = 0; it < 16; it++) {
            int idx = tid + it * 256;      // 0..4095
            int c  = idx >> 5;             // 0..127
            int k4 = (idx & 31) << 2;      // 0,4,...,124
            float4 w4 = *(const float4*)(Wm + c * D + k4);
            Bs[(k4 + 0) * SA + c] = w4.x;
            Bs[(k4 + 1) * SA + c] = w4.y;
            Bs[(k4 + 2) * SA + c] = w4.z;
            Bs[(k4 + 3) * SA + c] = w4.w;
        }
        __syncthreads();

        ull acc[4][4];
#pragma unroll
        for (int u = 0; u < 4; u++)
#pragma unroll
            for (int v = 0; v < 4; v++) acc[u][v] = 0ULL;

#pragma unroll 4
        for (int k = 0; k < D; k++) {
            ull aa[4];
#pragma unroll
            for (int u = 0; u < 4; u++) aa[u] = pack_dup(Ap[u * SA + k]);
            const ull* bk = (const ull*)(Bs + k * SA) + tx;  // pair (2tx+32v, +1)
#pragma unroll
            for (int v = 0; v < 4; v++) {
                ull bb = bk[16 * v];
#pragma unroll
                for (int u = 0; u < 4; u++) ffma2(acc[u][v], aa[u], bb);
            }
        }

        // Epilogue
        const float* bm = bias + m * D;
        float* OUT = (m == 0) ? OUT0 : OUT1;
#pragma unroll
        for (int u = 0; u < 4; u++) {
            int t = tb + ty * 4 + u;
            if (t < ntok) {
                int row = sidx ? sidx[t] : t;
                float* o = OUT + (size_t)row * D;
#pragma unroll
                for (int v = 0; v < 4; v++) {
                    int c = 2 * tx + 32 * v;
                    float2 r = unpack2(acc[u][v]);
                    float2 bi = *(const float2*)(bm + c);
                    r.x += bi.x; r.y += bi.y;
                    *(float2*)(o + c) = r;
                }
            }
        }
        if (NM > 1) __syncthreads();   // Bs reused next matrix
    }
}

// ---------------------------------------------------------------------------
// Attention: one block per window, warp h handles head h (d = 16).
// ---------------------------------------------------------------------------
template <int L>
__global__ __launch_bounds__(256)
void attn_kernel(const float* __restrict__ Q, const float* __restrict__ K,
                 const float* __restrict__ V, const int* __restrict__ ws,
                 float* __restrict__ AO)
{
    extern __shared__ float sm[];
    float* Ks = sm;                 // L x 129
    float* Vs = sm + L * 129;       // L x 129
    float* pb = Vs + L * 129;       // 8 warps x 64 probs
    const int w = blockIdx.x;
    const int t0 = ws[w];
    const int len = ws[w + 1] - t0;
    const int tid = threadIdx.x;

    for (int idx = tid; idx < len * D; idx += 256) {
        int r = idx >> 7, c = idx & 127;
        Ks[r * 129 + c] = K[(size_t)(t0 + r) * D + c];
        Vs[r * 129 + c] = V[(size_t)(t0 + r) * D + c];
    }
    __syncthreads();

    const int h = tid >> 5;
    const int lane = tid & 31;
    const int cb = h * 16;
    const int dd = lane & 15, half = lane >> 4;
    float* pbw = pb + h * 64;
    const float* kr0 = Ks + min(lane, len - 1) * 129 + cb;
    const float* kr1 = (L > 32) ? (Ks + min(lane + 32, len - 1) * 129 + cb) : kr0;

    for (int i = 0; i < len; i++) {
        float qv = 0.f;
        if (lane < 16) qv = Q[(size_t)(t0 + i) * D + cb + lane];
        float s0 = 0.f, s1 = 0.f;
#pragma unroll
        for (int d = 0; d < 16; d++) {
            float qd = __shfl_sync(0xffffffffu, qv, d);
            s0 += qd * kr0[d];
            if (L > 32) s1 += qd * kr1[d];
        }
        s0 = (lane < len) ? s0 * 0.25f : -1e30f;
        s1 = (L > 32 && lane + 32 < len) ? s1 * 0.25f : -1e30f;
        float m = fmaxf(s0, s1);
#pragma unroll
        for (int o = 16; o > 0; o >>= 1)
            m = fmaxf(m, __shfl_xor_sync(0xffffffffu, m, o));
        float p0 = (lane < len) ? __expf(s0 - m) : 0.f;
        float p1 = (L > 32 && lane + 32 < len) ? __expf(s1 - m) : 0.f;
        float dsum = p0 + p1;
#pragma unroll
        for (int o = 16; o > 0; o >>= 1)
            dsum += __shfl_xor_sync(0xffffffffu, dsum, o);
        float inv = 1.f / dsum;
        pbw[lane] = p0 * inv;
        if (L > 32) pbw[lane + 32] = p1 * inv;
        __syncwarp();

        float accv = 0.f;
        for (int j = half; j < len; j += 2)
            accv += pbw[j] * Vs[j * 129 + cb + dd];
        accv += __shfl_xor_sync(0xffffffffu, accv, 16);
        if (lane < 16) AO[(size_t)(t0 + i) * D + cb + lane] = accv;
        __syncwarp();
    }
}

// ---------------------------------------------------------------------------
extern "C" void kernel_launch(void* const* d_in, const int* in_sizes, int n_in,
                              void* d_out, int out_size)
{
    const float* feat  = (const float*)d_in[0];
    const float* pos16 = (const float*)d_in[1];
    const float* pos64 = (const float*)d_in[2];
    const float* Win   = (const float*)d_in[3];
    const float* bin   = (const float*)d_in[4];
    const float* Wout  = (const float*)d_in[5];
    const float* bout  = (const float*)d_in[6];
    const int* vox16 = (const int*)d_in[7];
    const int* fp16  = (const int*)d_in[8];
    const int* vox64 = (const int*)d_in[9];
    const int* fp64  = (const int*)d_in[10];
    const int n16  = in_sizes[7];
    const int n64  = in_sizes[9];
    const int nw16 = in_sizes[1] / (16 * D);
    const int nw64 = in_sizes[2] / (64 * D);
    float* out = (float*)d_out;

    float* scr = nullptr;
    cudaGetSymbolAddress((void**)&scr, g_scr);
    int* ws16 = nullptr; cudaGetSymbolAddress((void**)&ws16, g_ws16);
    int* ws64 = nullptr; cudaGetSymbolAddress((void**)&ws64, g_ws64);
    float* Qb = scr;
    float* Kb = scr + (size_t)NMAX * D;
    float* Vb = scr + (size_t)2 * NMAX * D;
    float* AO = scr + (size_t)3 * NMAX * D;

    const size_t gsm   = (64 * SA + 128 * SA) * sizeof(float);     // 99840 B
    const size_t asm16 = (2 * 16 * 129 + 8 * 64) * sizeof(float);
    const size_t asm64 = (2 * 64 * 129 + 8 * 64) * sizeof(float);  // 68096 B
    cudaFuncSetAttribute((const void*)gemm_tok<true, 2>,  cudaFuncAttributeMaxDynamicSharedMemorySize, (int)gsm);
    cudaFuncSetAttribute((const void*)gemm_tok<false, 1>, cudaFuncAttributeMaxDynamicSharedMemorySize, (int)gsm);
    cudaFuncSetAttribute((const void*)attn_kernel<64>, cudaFuncAttributeMaxDynamicSharedMemorySize, (int)asm64);

    build_ws<<<(n16 + 255) / 256, 256>>>(fp16, n16, 16, ws16, nw16);
    build_ws<<<(n64 + 255) / 256, 256>>>(fp64, n64, 64, ws64, nw64);

    const int gb16 = (n16 + 63) / 64, gb64 = (n64 + 63) / 64;
    const size_t off = (size_t)n16 * D;

    // Fused Q+K projection (A tile = gather(feat)+pos loaded once), V separate.
    gemm_tok<true, 2><<<gb16, 256, gsm>>>(feat, vox16, pos16, fp16, Win, bin,
                                          Qb, Kb, nullptr, n16);
    gemm_tok<false, 1><<<gb16, 256, gsm>>>(feat, vox16, nullptr, nullptr,
                                           Win + 256 * D, bin + 256, Vb, nullptr, nullptr, n16);
    gemm_tok<true, 2><<<gb64, 256, gsm>>>(feat, vox64, pos64, fp64, Win, bin,
                                          Qb + off, Kb + off, nullptr, n64);
    gemm_tok<false, 1><<<gb64, 256, gsm>>>(feat, vox64, nullptr, nullptr,
                                           Win + 256 * D, bin + 256, Vb + off, nullptr, nullptr, n64);

    // Per-window attention
    attn_kernel<16><<<nw16, 256, asm16>>>(Qb, Kb, Vb, ws16, AO);
    attn_kernel<64><<<nw64, 256, asm64>>>(Qb + off, Kb + off, Vb + off, ws64, AO + off);

    // Output projection, scattered straight into d_out
    gemm_tok<false, 1><<<gb16, 256, gsm>>>(AO, nullptr, nullptr, nullptr,
                                           Wout, bout, out, nullptr, vox16, n16);
    gemm_tok<false, 1><<<gb64, 256, gsm>>>(AO + off, nullptr, nullptr, nullptr,
                                           Wout, bout, out, nullptr, vox64, n64);
}

// round 3
// speedup vs baseline: 1.3265x; 1.3265x over previous
#include <cuda_runtime.h>
#include <math.h>

#define D 128
#define NMAX 210048
#define SA 130   // even smem stride -> 8B-aligned float2 rows for LDS.64

// Scratch: Q, K, V, attention-out  (4 * NMAX * 128 floats ~ 430 MB, static)
__device__ float g_scr[(size_t)4 * NMAX * D];
__device__ int g_ws16[20002];
__device__ int g_ws64[8002];

typedef unsigned long long ull;

__device__ __forceinline__ ull pack_dup(float a) {
    ull r;
    asm("mov.b64 %0, {%1, %1};" : "=l"(r) : "f"(a));
    return r;
}
__device__ __forceinline__ void ffma2(ull& acc, ull a, ull b) {
    asm("fma.rn.f32x2 %0, %1, %2, %0;" : "+l"(acc) : "l"(a), "l"(b));
}
__device__ __forceinline__ float2 unpack2(ull v) {
    float2 r;
    asm("mov.b64 {%0, %1}, %2;" : "=f"(r.x), "=f"(r.y) : "l"(v));
    return r;
}

// ---------------------------------------------------------------------------
// Window-start builder (flat_pos strictly increasing -> contiguous ranges).
// ---------------------------------------------------------------------------
__global__ void build_ws(const int* __restrict__ fp, int n, int L,
                         int* __restrict__ ws, int nw)
{
    int i = blockIdx.x * blockDim.x + threadIdx.x;
    if (i < n) {
        int w = fp[i] / L;
        if (i == 0 || fp[i - 1] / L != w) ws[w] = i;
    }
    if (i == 0) ws[nw] = n;
}

// ---------------------------------------------------------------------------
// Tiled GEMM (fp32, at FFMA roofline). 64 tokens x 128 ch per block, K=128.
// ---------------------------------------------------------------------------
template <bool ADD_POS, int NM>
__global__ __launch_bounds__(256)
void gemm_tok(const float* __restrict__ X, const int* __restrict__ gidx,
              const float* __restrict__ POS, const int* __restrict__ fp,
              const float* __restrict__ W, const float* __restrict__ bias,
              float* __restrict__ OUT0, float* __restrict__ OUT1,
              const int* __restrict__ sidx, int ntok)
{
    extern __shared__ float sm[];
    float* As = sm;              // 64 x SA
    float* Bs = sm + 64 * SA;    // 128 x SA (k-major)
    const int tid = threadIdx.x;
    const int tb = blockIdx.x * 64;

#pragma unroll
    for (int it = 0; it < 8; it++) {
        int idx = tid + it * 256;
        int r  = idx >> 5;
        int c4 = (idx & 31) << 2;
        int t  = tb + r;
        float4 v = make_float4(0.f, 0.f, 0.f, 0.f);
        if (t < ntok) {
            int src = gidx ? gidx[t] : t;
            v = *(const float4*)(X + (size_t)src * D + c4);
            if (ADD_POS) {
                float4 p = *(const float4*)(POS + (size_t)fp[t] * D + c4);
                v.x += p.x; v.y += p.y; v.z += p.z; v.w += p.w;
            }
        }
        As[r * SA + c4 + 0] = v.x;
        As[r * SA + c4 + 1] = v.y;
        As[r * SA + c4 + 2] = v.z;
        As[r * SA + c4 + 3] = v.w;
    }

    const int tx = tid & 15;
    const int ty = tid >> 4;
    const float* Ap = As + ty * 4 * SA;

#pragma unroll
    for (int m = 0; m < NM; m++) {
        const float* Wm = W + (size_t)m * D * D;
#pragma unroll
        for (int it = 0; it < 16; it++) {
            int idx = tid + it * 256;
            int c  = idx >> 5;
            int k4 = (idx & 31) << 2;
            float4 w4 = *(const float4*)(Wm + c * D + k4);
            Bs[(k4 + 0) * SA + c] = w4.x;
            Bs[(k4 + 1) * SA + c] = w4.y;
            Bs[(k4 + 2) * SA + c] = w4.z;
            Bs[(k4 + 3) * SA + c] = w4.w;
        }
        __syncthreads();

        ull acc[4][4];
#pragma unroll
        for (int u = 0; u < 4; u++)
#pragma unroll
            for (int v = 0; v < 4; v++) acc[u][v] = 0ULL;

#pragma unroll 4
        for (int k = 0; k < D; k++) {
            ull aa[4];
#pragma unroll
            for (int u = 0; u < 4; u++) aa[u] = pack_dup(Ap[u * SA + k]);
            const ull* bk = (const ull*)(Bs + k * SA) + tx;
#pragma unroll
            for (int v = 0; v < 4; v++) {
                ull bb = bk[16 * v];
#pragma unroll
                for (int u = 0; u < 4; u++) ffma2(acc[u][v], aa[u], bb);
            }
        }

        const float* bm = bias + m * D;
        float* OUT = (m == 0) ? OUT0 : OUT1;
#pragma unroll
        for (int u = 0; u < 4; u++) {
            int t = tb + ty * 4 + u;
            if (t < ntok) {
                int row = sidx ? sidx[t] : t;
                float* o = OUT + (size_t)row * D;
#pragma unroll
                for (int v = 0; v < 4; v++) {
                    int c = 2 * tx + 32 * v;
                    float2 r = unpack2(acc[u][v]);
                    float2 bi = *(const float2*)(bm + c);
                    r.x += bi.x; r.y += bi.y;
                    *(float2*)(o + c) = r;
                }
            }
        }
        if (NM > 1) __syncthreads();
    }
}

// ---------------------------------------------------------------------------
// Attention v2: one THREAD per (query, head). No shuffles, no serial q-loop.
//   K/V staged in smem, chunk-swizzled: head-h phase-p 16B chunk stored at
//   chunk slot p*8+h  ->  8 heads of a warp hit 8 distinct bank slots.
//   REGSCORE: keep the <=16 scores in registers (skip K re-read in pass 2).
// ---------------------------------------------------------------------------
template <int L, int TPB, bool REGSCORE>
__global__ __launch_bounds__(TPB)
void attn_kernel(const float* __restrict__ Q, const float* __restrict__ K,
                 const float* __restrict__ V, const int* __restrict__ ws,
                 float* __restrict__ AO, int nw)
{
    constexpr int TPW = L * 8;           // threads per window
    constexpr int WPB = TPB / TPW;       // windows per block
    extern __shared__ float4 sm4[];      // [WPB][2][L*32]
    const int tid = threadIdx.x;
    const int wl  = tid / TPW;
    const int w   = blockIdx.x * WPB + wl;
    float4* Ks = sm4 + (size_t)wl * (2 * L * 32);
    float4* Vs = Ks + L * 32;

    int t0 = 0, len = 0;
    if (w < nw) { t0 = ws[w]; len = ws[w + 1] - t0; }

    const int lt = tid - wl * TPW;       // 0..TPW-1
    // cooperative swizzled load of K,V rows [t0, t0+len)
    for (int idx = lt; idx < len * 32; idx += TPW) {
        int j = idx >> 5, g = idx & 31;      // g: float4 index in row
        int h = g >> 2,  p = g & 3;
        int chunk = p * 8 + h;
        Ks[j * 32 + chunk] = ((const float4*)K)[(size_t)(t0 + j) * 32 + g];
        Vs[j * 32 + chunk] = ((const float4*)V)[(size_t)(t0 + j) * 32 + g];
    }
    __syncthreads();

    const int q = lt >> 3;
    const int h = lt & 7;
    if (w >= nw || q >= len) return;

    // q vector (16 floats for this head)
    float4 qv[4];
    const float4* Qp = (const float4*)Q + (size_t)(t0 + q) * 32 + h * 4;
#pragma unroll
    for (int p = 0; p < 4; p++) qv[p] = Qp[p];

    float sreg[REGSCORE ? L : 1];

    // pass 1: scores + max
    float m = -1e30f;
    for (int j = 0; j < len; j++) {
        const float4* kr = Ks + j * 32 + h;
        float s = 0.f;
#pragma unroll
        for (int p = 0; p < 4; p++) {
            float4 kk = kr[p * 8];
            s += qv[p].x * kk.x + qv[p].y * kk.y + qv[p].z * kk.z + qv[p].w * kk.w;
        }
        if (REGSCORE) sreg[j < L ? j : 0] = s;
        m = fmaxf(m, s);
    }
    const float m25 = m * 0.25f;

    // pass 2: exp + PV
    float acc[16];
#pragma unroll
    for (int e = 0; e < 16; e++) acc[e] = 0.f;
    float denom = 0.f;

    for (int j = 0; j < len; j++) {
        float s;
        if (REGSCORE) {
            s = sreg[j < L ? j : 0];
        } else {
            const float4* kr = Ks + j * 32 + h;
            s = 0.f;
#pragma unroll
            for (int p = 0; p < 4; p++) {
                float4 kk = kr[p * 8];
                s += qv[p].x * kk.x + qv[p].y * kk.y + qv[p].z * kk.z + qv[p].w * kk.w;
            }
        }
        float pr = __expf(s * 0.25f - m25);     // scale = 1/sqrt(16)
        denom += pr;
        const float4* vr = Vs + j * 32 + h;
#pragma unroll
        for (int p = 0; p < 4; p++) {
            float4 vv = vr[p * 8];
            acc[p * 4 + 0] += pr * vv.x;
            acc[p * 4 + 1] += pr * vv.y;
            acc[p * 4 + 2] += pr * vv.z;
            acc[p * 4 + 3] += pr * vv.w;
        }
    }

    const float inv = 1.f / denom;
    float4* o = (float4*)(AO + (size_t)(t0 + q) * D + h * 16);
#pragma unroll
    for (int p = 0; p < 4; p++)
        o[p] = make_float4(acc[p * 4 + 0] * inv, acc[p * 4 + 1] * inv,
                           acc[p * 4 + 2] * inv, acc[p * 4 + 3] * inv);
}

// ---------------------------------------------------------------------------
extern "C" void kernel_launch(void* const* d_in, const int* in_sizes, int n_in,
                              void* d_out, int out_size)
{
    const float* feat  = (const float*)d_in[0];
    const float* pos16 = (const float*)d_in[1];
    const float* pos64 = (const float*)d_in[2];
    const float* Win   = (const float*)d_in[3];
    const float* bin   = (const float*)d_in[4];
    const float* Wout  = (const float*)d_in[5];
    const float* bout  = (const float*)d_in[6];
    const int* vox16 = (const int*)d_in[7];
    const int* fp16  = (const int*)d_in[8];
    const int* vox64 = (const int*)d_in[9];
    const int* fp64  = (const int*)d_in[10];
    const int n16  = in_sizes[7];
    const int n64  = in_sizes[9];
    const int nw16 = in_sizes[1] / (16 * D);
    const int nw64 = in_sizes[2] / (64 * D);
    float* out = (float*)d_out;

    float* scr = nullptr;
    cudaGetSymbolAddress((void**)&scr, g_scr);
    int* ws16 = nullptr; cudaGetSymbolAddress((void**)&ws16, g_ws16);
    int* ws64 = nullptr; cudaGetSymbolAddress((void**)&ws64, g_ws64);
    float* Qb = scr;
    float* Kb = scr + (size_t)NMAX * D;
    float* Vb = scr + (size_t)2 * NMAX * D;
    float* AO = scr + (size_t)3 * NMAX * D;

    const size_t gsm   = (64 * SA + 128 * SA) * sizeof(float);     // 99840 B
    const size_t asm16 = (size_t)2 * 2 * 16 * 32 * sizeof(float4); // 32 KB
    const size_t asm64 = (size_t)1 * 2 * 64 * 32 * sizeof(float4); // 64 KB
    cudaFuncSetAttribute((const void*)gemm_tok<true, 2>,  cudaFuncAttributeMaxDynamicSharedMemorySize, (int)gsm);
    cudaFuncSetAttribute((const void*)gemm_tok<false, 1>, cudaFuncAttributeMaxDynamicSharedMemorySize, (int)gsm);
    cudaFuncSetAttribute((const void*)attn_kernel<64, 512, false>, cudaFuncAttributeMaxDynamicSharedMemorySize, (int)asm64);
    cudaFuncSetAttribute((const void*)attn_kernel<16, 256, true>,  cudaFuncAttributeMaxDynamicSharedMemorySize, (int)asm16);

    build_ws<<<(n16 + 255) / 256, 256>>>(fp16, n16, 16, ws16, nw16);
    build_ws<<<(n64 + 255) / 256, 256>>>(fp64, n64, 64, ws64, nw64);

    const int gb16 = (n16 + 63) / 64, gb64 = (n64 + 63) / 64;
    const size_t off = (size_t)n16 * D;

    // Fused Q+K projection (A tile loaded once), V separate.
    gemm_tok<true, 2><<<gb16, 256, gsm>>>(feat, vox16, pos16, fp16, Win, bin,
                                          Qb, Kb, nullptr, n16);
    gemm_tok<false, 1><<<gb16, 256, gsm>>>(feat, vox16, nullptr, nullptr,
                                           Win + 256 * D, bin + 256, Vb, nullptr, nullptr, n16);
    gemm_tok<true, 2><<<gb64, 256, gsm>>>(feat, vox64, pos64, fp64, Win, bin,
                                          Qb + off, Kb + off, nullptr, n64);
    gemm_tok<false, 1><<<gb64, 256, gsm>>>(feat, vox64, nullptr, nullptr,
                                           Win + 256 * D, bin + 256, Vb + off, nullptr, nullptr, n64);

    // Per-window attention (thread per query-head)
    attn_kernel<16, 256, true ><<<(nw16 + 1) / 2, 256, asm16>>>(Qb, Kb, Vb, ws16, AO, nw16);
    attn_kernel<64, 512, false><<<nw64, 512, asm64>>>(Qb + off, Kb + off, Vb + off, ws64, AO + off, nw64);

    // Output projection, scattered straight into d_out
    gemm_tok<false, 1><<<gb16, 256, gsm>>>(AO, nullptr, nullptr, nullptr,
                                           Wout, bout, out, nullptr, vox16, n16);
    gemm_tok<false, 1><<<gb64, 256, gsm>>>(AO + off, nullptr, nullptr, nullptr,
                                           Wout, bout, out, nullptr, vox64, n64);
}

// round 5
// speedup vs baseline: 2.2081x; 1.6645x over previous
#include <cuda_runtime.h>
#include <math.h>

#define D 128
#define NMAX 210048
#define SAK 132   // As stride: (4g+t)%32 distinct per lane -> conflict-free frags

// Scratch: Q, K, V, attention-out  (~430 MB, static)
__device__ float g_scr[(size_t)4 * NMAX * D];
__device__ float g_wpack[4 * D * D];   // mma-fragment-packed weights (tf32)
__device__ int g_ws16[20002];
__device__ int g_ws64[8002];

__device__ __forceinline__ float to_tf32(float x) {
    asm("cvt.rna.tf32.f32 %0, %0;" : "+f"(x));
    return x;
}

// ---------------------------------------------------------------------------
// Window-start builder (flat_pos strictly increasing -> contiguous ranges).
// ---------------------------------------------------------------------------
__global__ void build_ws(const int* __restrict__ fp, int n, int L,
                         int* __restrict__ ws, int nw)
{
    int i = blockIdx.x * blockDim.x + threadIdx.x;
    if (i < n) {
        int w = fp[i] / L;
        if (i == 0 || fp[i - 1] / L != w) ws[w] = i;
    }
    if (i == 0) ws[nw] = n;
}

// ---------------------------------------------------------------------------
// Pack W into m16n8k8 B-fragment order, tf32-rounded.
//   g_wpack[m][ks][nf][lane] = float2( W[nf*8+g][ks*8+t], W[nf*8+g][ks*8+t+4] )
//   (g = lane>>2, t = lane&3;  B[k][n] = W[n][k] for OUT = A @ W^T)
// ---------------------------------------------------------------------------
__global__ void pack_w(const float* __restrict__ Win, const float* __restrict__ Wout)
{
    int i = blockIdx.x * blockDim.x + threadIdx.x;   // 0..32767
    if (i >= 4 * 16 * 16 * 32) return;
    int lane = i & 31;
    int nf = (i >> 5) & 15;
    int ks = (i >> 9) & 15;
    int m  = i >> 13;
    int g = lane >> 2, t = lane & 3;
    const float* W = (m < 3) ? (Win + (size_t)m * D * D) : Wout;
    int row = nf * 8 + g;
    int col = ks * 8 + t;
    float w0 = to_tf32(W[row * D + col]);
    float w1 = to_tf32(W[row * D + col + 4]);
    ((float2*)g_wpack)[i] = make_float2(w0, w1);
}

// ---------------------------------------------------------------------------
// TF32 tensor-core GEMM: OUT[row(t)] = X[src(t)] (+POS) @ W^T + bias
//   Block: 64 tokens x 128 channels, 128 threads = 4 warps, warp tile 32x64.
//   NM=2 fuses Q+K (A staged once).
// ---------------------------------------------------------------------------
template <bool ADD_POS, int NM>
__global__ __launch_bounds__(128)
void gemm_mma(const float* __restrict__ X, const int* __restrict__ gidx,
              const float* __restrict__ POS, const int* __restrict__ fp,
              int wmat, const float* __restrict__ bias,
              float* __restrict__ OUT0, float* __restrict__ OUT1,
              const int* __restrict__ sidx, int ntok)
{
    extern __shared__ float sm[];
    float* As = sm;                                 // 64 x SAK
    float2* Bf = (float2*)(sm + 64 * SAK);          // [16][16][32] float2 = 64KB
    const int tid = threadIdx.x;
    const int tb = blockIdx.x * 64;

    // Stage A (gather + optional pos), tf32-rounded
#pragma unroll
    for (int it = 0; it < 16; it++) {
        int idx = tid + it * 128;          // 0..2047 float4 slots
        int r  = idx >> 5;
        int c4 = (idx & 31) << 2;
        int tk = tb + r;
        float4 v = make_float4(0.f, 0.f, 0.f, 0.f);
        if (tk < ntok) {
            int src = gidx ? gidx[tk] : tk;
            v = *(const float4*)(X + (size_t)src * D + c4);
            if (ADD_POS) {
                float4 p = *(const float4*)(POS + (size_t)fp[tk] * D + c4);
                v.x += p.x; v.y += p.y; v.z += p.z; v.w += p.w;
            }
        }
        As[r * SAK + c4 + 0] = to_tf32(v.x);
        As[r * SAK + c4 + 1] = to_tf32(v.y);
        As[r * SAK + c4 + 2] = to_tf32(v.z);
        As[r * SAK + c4 + 3] = to_tf32(v.w);
    }

    const int w  = tid >> 5, lane = tid & 31;
    const int wm = w & 1,  wn = w >> 1;
    const int g  = lane >> 2, t4 = lane & 3;
    const unsigned* Asu = (const unsigned*)As;

#pragma unroll
    for (int m = 0; m < NM; m++) {
        // Stage packed B fragments (straight float4 copy; reads are seq LDS.64)
        {
            const float4* src = (const float4*)g_wpack + (size_t)(wmat + m) * 4096;
            float4* dstB = (float4*)Bf;
#pragma unroll
            for (int it = 0; it < 32; it++)
                dstB[tid + it * 128] = src[tid + it * 128];
        }
        __syncthreads();

        float acc[2][8][4];
#pragma unroll
        for (int ma = 0; ma < 2; ma++)
#pragma unroll
            for (int nf = 0; nf < 8; nf++)
#pragma unroll
                for (int e = 0; e < 4; e++) acc[ma][nf][e] = 0.f;

        const unsigned* ap = Asu + (wm * 32 + g) * SAK + t4;
        const float2*   bp = Bf + (size_t)(wn * 8) * 32 + lane;

#pragma unroll
        for (int ks = 0; ks < 16; ks++) {
            unsigned a[2][4];
#pragma unroll
            for (int ma = 0; ma < 2; ma++) {
                const unsigned* ar = ap + ma * 16 * SAK + ks * 8;
                a[ma][0] = ar[0];
                a[ma][1] = ar[8 * SAK];
                a[ma][2] = ar[4];
                a[ma][3] = ar[8 * SAK + 4];
            }
#pragma unroll
            for (int nf = 0; nf < 8; nf++) {
                float2 bv = bp[(ks * 16 + nf) * 32];
                unsigned b0 = __float_as_uint(bv.x);
                unsigned b1 = __float_as_uint(bv.y);
#pragma unroll
                for (int ma = 0; ma < 2; ma++) {
                    asm volatile(
                        "mma.sync.aligned.m16n8k8.row.col.f32.tf32.tf32.f32 "
                        "{%0,%1,%2,%3}, {%4,%5,%6,%7}, {%8,%9}, {%0,%1,%2,%3};"
                        : "+f"(acc[ma][nf][0]), "+f"(acc[ma][nf][1]),
                          "+f"(acc[ma][nf][2]), "+f"(acc[ma][nf][3])
                        : "r"(a[ma][0]), "r"(a[ma][1]), "r"(a[ma][2]), "r"(a[ma][3]),
                          "r"(b0), "r"(b1));
                }
            }
        }

        // Epilogue: c0,c1 -> row g, cols 2t,2t+1; c2,c3 -> row g+8
        const float* bm = bias + m * D;
        float* OUT = (m == 0) ? OUT0 : OUT1;
#pragma unroll
        for (int ma = 0; ma < 2; ma++) {
#pragma unroll
            for (int rr = 0; rr < 2; rr++) {
                int r = tb + wm * 32 + ma * 16 + g + rr * 8;
                if (r < ntok) {
                    int rowg = sidx ? sidx[r] : r;
                    float* o = OUT + (size_t)rowg * D;
#pragma unroll
                    for (int nf = 0; nf < 8; nf++) {
                        int c = wn * 64 + nf * 8 + 2 * t4;
                        float2 bi = *(const float2*)(bm + c);
                        float2 val = make_float2(acc[ma][nf][rr * 2 + 0] + bi.x,
                                                 acc[ma][nf][rr * 2 + 1] + bi.y);
                        *(float2*)(o + c) = val;
                    }
                }
            }
        }
        if (NM > 1) __syncthreads();
    }
}

// ---------------------------------------------------------------------------
// Attention: one thread per (query, head); chunk-swizzled K/V smem.
// ---------------------------------------------------------------------------
template <int L, int TPB, bool REGSCORE>
__global__ __launch_bounds__(TPB)
void attn_kernel(const float* __restrict__ Q, const float* __restrict__ K,
                 const float* __restrict__ V, const int* __restrict__ ws,
                 float* __restrict__ AO, int nw)
{
    constexpr int TPW = L * 8;
    constexpr int WPB = TPB / TPW;
    extern __shared__ float4 sm4[];
    const int tid = threadIdx.x;
    const int wl  = tid / TPW;
    const int w   = blockIdx.x * WPB + wl;
    float4* Ks = sm4 + (size_t)wl * (2 * L * 32);
    float4* Vs = Ks + L * 32;

    int t0 = 0, len = 0;
    if (w < nw) { t0 = ws[w]; len = ws[w + 1] - t0; }

    const int lt = tid - wl * TPW;
    for (int idx = lt; idx < len * 32; idx += TPW) {
        int j = idx >> 5, gg = idx & 31;
        int h = gg >> 2, p = gg & 3;
        int chunk = p * 8 + h;
        Ks[j * 32 + chunk] = ((const float4*)K)[(size_t)(t0 + j) * 32 + gg];
        Vs[j * 32 + chunk] = ((const float4*)V)[(size_t)(t0 + j) * 32 + gg];
    }
    __syncthreads();

    const int q = lt >> 3;
    const int h = lt & 7;
    if (w >= nw || q >= len) return;

    float4 qv[4];
    const float4* Qp = (const float4*)Q + (size_t)(t0 + q) * 32 + h * 4;
#pragma unroll
    for (int p = 0; p < 4; p++) qv[p] = Qp[p];

    float sreg[REGSCORE ? L : 1];

    float m = -1e30f;
    for (int j = 0; j < len; j++) {
        const float4* kr = Ks + j * 32 + h;
        float s = 0.f;
#pragma unroll
        for (int p = 0; p < 4; p++) {
            float4 kk = kr[p * 8];
            s += qv[p].x * kk.x + qv[p].y * kk.y + qv[p].z * kk.z + qv[p].w * kk.w;
        }
        if (REGSCORE) sreg[j < L ? j : 0] = s;
        m = fmaxf(m, s);
    }
    const float m25 = m * 0.25f;

    float acc[16];
#pragma unroll
    for (int e = 0; e < 16; e++) acc[e] = 0.f;
    float denom = 0.f;

    for (int j = 0; j < len; j++) {
        float s;
        if (REGSCORE) {
            s = sreg[j < L ? j : 0];
        } else {
            const float4* kr = Ks + j * 32 + h;
            s = 0.f;
#pragma unroll
            for (int p = 0; p < 4; p++) {
                float4 kk = kr[p * 8];
                s += qv[p].x * kk.x + qv[p].y * kk.y + qv[p].z * kk.z + qv[p].w * kk.w;
            }
        }
        float pr = __expf(s * 0.25f - m25);
        denom += pr;
        const float4* vr = Vs + j * 32 + h;
#pragma unroll
        for (int p = 0; p < 4; p++) {
            float4 vv = vr[p * 8];
            acc[p * 4 + 0] += pr * vv.x;
            acc[p * 4 + 1] += pr * vv.y;
            acc[p * 4 + 2] += pr * vv.z;
            acc[p * 4 + 3] += pr * vv.w;
        }
    }

    const float inv = 1.f / denom;
    float4* o = (float4*)(AO + (size_t)(t0 + q) * D + h * 16);
#pragma unroll
    for (int p = 0; p < 4; p++)
        o[p] = make_float4(acc[p * 4 + 0] * inv, acc[p * 4 + 1] * inv,
                           acc[p * 4 + 2] * inv, acc[p * 4 + 3] * inv);
}

// ---------------------------------------------------------------------------
extern "C" void kernel_launch(void* const* d_in, const int* in_sizes, int n_in,
                              void* d_out, int out_size)
{
    const float* feat  = (const float*)d_in[0];
    const float* pos16 = (const float*)d_in[1];
    const float* pos64 = (const float*)d_in[2];
    const float* Win   = (const float*)d_in[3];
    const float* bin   = (const float*)d_in[4];
    const float* Wout  = (const float*)d_in[5];
    const float* bout  = (const float*)d_in[6];
    const int* vox16 = (const int*)d_in[7];
    const int* fp16  = (const int*)d_in[8];
    const int* vox64 = (const int*)d_in[9];
    const int* fp64  = (const int*)d_in[10];
    const int n16  = in_sizes[7];
    const int n64  = in_sizes[9];
    const int nw16 = in_sizes[1] / (16 * D);
    const int nw64 = in_sizes[2] / (64 * D);
    float* out = (float*)d_out;

    float* scr = nullptr;
    cudaGetSymbolAddress((void**)&scr, g_scr);
    int* ws16 = nullptr; cudaGetSymbolAddress((void**)&ws16, g_ws16);
    int* ws64 = nullptr; cudaGetSymbolAddress((void**)&ws64, g_ws64);
    float* Qb = scr;
    float* Kb = scr + (size_t)NMAX * D;
    float* Vb = scr + (size_t)2 * NMAX * D;
    float* AO = scr + (size_t)3 * NMAX * D;

    const size_t gsm   = 64 * SAK * sizeof(float) + 16 * 16 * 32 * sizeof(float2); // 99328
    const size_t asm16 = (size_t)2 * 2 * 16 * 32 * sizeof(float4); // 32 KB
    const size_t asm64 = (size_t)1 * 2 * 64 * 32 * sizeof(float4); // 64 KB
    cudaFuncSetAttribute((const void*)gemm_mma<true, 2>,  cudaFuncAttributeMaxDynamicSharedMemorySize, (int)gsm);
    cudaFuncSetAttribute((const void*)gemm_mma<false, 1>, cudaFuncAttributeMaxDynamicSharedMemorySize, (int)gsm);
    cudaFuncSetAttribute((const void*)attn_kernel<64, 512, false>, cudaFuncAttributeMaxDynamicSharedMemorySize, (int)asm64);
    cudaFuncSetAttribute((const void*)attn_kernel<16, 256, true>,  cudaFuncAttributeMaxDynamicSharedMemorySize, (int)asm16);

    build_ws<<<(n16 + 255) / 256, 256>>>(fp16, n16, 16, ws16, nw16);
    build_ws<<<(n64 + 255) / 256, 256>>>(fp64, n64, 64, ws64, nw64);
    pack_w<<<128, 256>>>(Win, Wout);

    const int gb16 = (n16 + 63) / 64, gb64 = (n64 + 63) / 64;
    const size_t off = (size_t)n16 * D;

    // Fused Q+K projection (A staged once), V separate.  wmat: 0=Wq,1=Wk,2=Wv,3=Wout
    gemm_mma<true, 2><<<gb16, 128, gsm>>>(feat, vox16, pos16, fp16, 0, bin,
                                          Qb, Kb, nullptr, n16);
    gemm_mma<false, 1><<<gb16, 128, gsm>>>(feat, vox16, nullptr, nullptr, 2, bin + 256,
                                           Vb, nullptr, nullptr, n16);
    gemm_mma<true, 2><<<gb64, 128, gsm>>>(feat, vox64, pos64, fp64, 0, bin,
                                          Qb + off, Kb + off, nullptr, n64);
    gemm_mma<false, 1><<<gb64, 128, gsm>>>(feat, vox64, nullptr, nullptr, 2, bin + 256,
                                           Vb + off, nullptr, nullptr, n64);

    // Per-window attention (thread per query-head)
    attn_kernel<16, 256, true ><<<(nw16 + 1) / 2, 256, asm16>>>(Qb, Kb, Vb, ws16, AO, nw16);
    attn_kernel<64, 512, false><<<nw64, 512, asm64>>>(Qb + off, Kb + off, Vb + off, ws64, AO + off, nw64);

    // Output projection, scattered straight into d_out
    gemm_mma<false, 1><<<gb16, 128, gsm>>>(AO, nullptr, nullptr, nullptr, 3, bout,
                                           out, nullptr, vox16, n16);
    gemm_mma<false, 1><<<gb64, 128, gsm>>>(AO + off, nullptr, nullptr, nullptr, 3, bout,
                                           out, nullptr, vox64, n64);
}

// round 7
// speedup vs baseline: 2.5918x; 1.1738x over previous
#include <cuda_runtime.h>
#include <math.h>

#define D 128
#define NMAX 210048
#define SAK 132   // As stride: (4g+t)%32 distinct per lane -> conflict-free frags

// Scratch: Q, K, V, attention-out  (~430 MB, static)
__device__ float g_scr[(size_t)4 * NMAX * D];
__device__ float g_wpack[4 * D * D];   // mma-fragment-packed weights (tf32)
__device__ int g_ws16[20002];
__device__ int g_ws64[8002];

__device__ __forceinline__ float to_tf32(float x) {
    asm("cvt.rna.tf32.f32 %0, %0;" : "+f"(x));
    return x;
}

// ---------------------------------------------------------------------------
// Window-start builder (flat_pos strictly increasing -> contiguous ranges).
// ---------------------------------------------------------------------------
__global__ void build_ws(const int* __restrict__ fp, int n, int L,
                         int* __restrict__ ws, int nw)
{
    int i = blockIdx.x * blockDim.x + threadIdx.x;
    if (i < n) {
        int w = fp[i] / L;
        if (i == 0 || fp[i - 1] / L != w) ws[w] = i;
    }
    if (i == 0) ws[nw] = n;
}

// ---------------------------------------------------------------------------
// Pack W into m16n8k8 B-fragment order, tf32-rounded.
//   g_wpack[m][ks][nf][lane] = float2( W[nf*8+g][ks*8+t], W[nf*8+g][ks*8+t+4] )
// ---------------------------------------------------------------------------
__global__ void pack_w(const float* __restrict__ Win, const float* __restrict__ Wout)
{
    int i = blockIdx.x * blockDim.x + threadIdx.x;   // 0..32767
    if (i >= 4 * 16 * 16 * 32) return;
    int lane = i & 31;
    int nf = (i >> 5) & 15;
    int ks = (i >> 9) & 15;
    int m  = i >> 13;
    int g = lane >> 2, t = lane & 3;
    const float* W = (m < 3) ? (Win + (size_t)m * D * D) : Wout;
    int row = nf * 8 + g;
    int col = ks * 8 + t;
    float w0 = to_tf32(W[row * D + col]);
    float w1 = to_tf32(W[row * D + col + 4]);
    ((float2*)g_wpack)[i] = make_float2(w0, w1);
}

// ---------------------------------------------------------------------------
// TF32 tensor-core GEMM, B fragments read straight from L1/L2 (no B smem).
//   Block: 64 tokens x 128 channels, 128 threads = 4 warps, warp tile 32x64.
// ---------------------------------------------------------------------------
template <bool ADD_POS, int NM>
__global__ __launch_bounds__(128, 4)
void gemm_mma(const float* __restrict__ X, const int* __restrict__ gidx,
              const float* __restrict__ POS, const int* __restrict__ fp,
              int wmat, const float* __restrict__ bias,
              float* __restrict__ OUT0, float* __restrict__ OUT1,
              const int* __restrict__ sidx, int ntok)
{
    extern __shared__ float sm[];
    float* As = sm;                                 // 64 x SAK = 33792 B
    const int tid = threadIdx.x;
    const int tb = blockIdx.x * 64;

    // Stage A (gather + optional pos), tf32-rounded
#pragma unroll
    for (int it = 0; it < 16; it++) {
        int idx = tid + it * 128;          // 0..2047 float4 slots
        int r  = idx >> 5;
        int c4 = (idx & 31) << 2;
        int tk = tb + r;
        float4 v = make_float4(0.f, 0.f, 0.f, 0.f);
        if (tk < ntok) {
            int src = gidx ? gidx[tk] : tk;
            v = *(const float4*)(X + (size_t)src * D + c4);
            if (ADD_POS) {
                float4 p = *(const float4*)(POS + (size_t)fp[tk] * D + c4);
                v.x += p.x; v.y += p.y; v.z += p.z; v.w += p.w;
            }
        }
        As[r * SAK + c4 + 0] = to_tf32(v.x);
        As[r * SAK + c4 + 1] = to_tf32(v.y);
        As[r * SAK + c4 + 2] = to_tf32(v.z);
        As[r * SAK + c4 + 3] = to_tf32(v.w);
    }
    __syncthreads();

    const int w  = tid >> 5, lane = tid & 31;
    const int wm = w & 1,  wn = w >> 1;
    const int g  = lane >> 2, t4 = lane & 3;
    const unsigned* Asu = (const unsigned*)As;

#pragma unroll
    for (int m = 0; m < NM; m++) {
        float acc[2][8][4];
#pragma unroll
        for (int ma = 0; ma < 2; ma++)
#pragma unroll
            for (int nf = 0; nf < 8; nf++)
#pragma unroll
                for (int e = 0; e < 4; e++) acc[ma][nf][e] = 0.f;

        const unsigned* ap = Asu + (wm * 32 + g) * SAK + t4;
        // B fragments from global (L1/L2-resident wpack), lane-contiguous LDG.64
        const float2* bp = (const float2*)g_wpack
                         + ((size_t)(wmat + m) * 256 + wn * 8) * 32 + lane;

#pragma unroll
        for (int ks = 0; ks < 16; ks++) {
            unsigned a[2][4];
#pragma unroll
            for (int ma = 0; ma < 2; ma++) {
                const unsigned* ar = ap + ma * 16 * SAK + ks * 8;
                a[ma][0] = ar[0];
                a[ma][1] = ar[8 * SAK];
                a[ma][2] = ar[4];
                a[ma][3] = ar[8 * SAK + 4];
            }
#pragma unroll
            for (int nf = 0; nf < 8; nf++) {
                float2 bv = __ldg(bp + (ks * 16 + nf) * 32);
                unsigned b0 = __float_as_uint(bv.x);
                unsigned b1 = __float_as_uint(bv.y);
#pragma unroll
                for (int ma = 0; ma < 2; ma++) {
                    asm volatile(
                        "mma.sync.aligned.m16n8k8.row.col.f32.tf32.tf32.f32 "
                        "{%0,%1,%2,%3}, {%4,%5,%6,%7}, {%8,%9}, {%0,%1,%2,%3};"
                        : "+f"(acc[ma][nf][0]), "+f"(acc[ma][nf][1]),
                          "+f"(acc[ma][nf][2]), "+f"(acc[ma][nf][3])
                        : "r"(a[ma][0]), "r"(a[ma][1]), "r"(a[ma][2]), "r"(a[ma][3]),
                          "r"(b0), "r"(b1));
                }
            }
        }

        // Epilogue: c0,c1 -> row g, cols 2t,2t+1; c2,c3 -> row g+8
        const float* bm = bias + m * D;
        float* OUT = (m == 0) ? OUT0 : OUT1;
#pragma unroll
        for (int ma = 0; ma < 2; ma++) {
#pragma unroll
            for (int rr = 0; rr < 2; rr++) {
                int r = tb + wm * 32 + ma * 16 + g + rr * 8;
                if (r < ntok) {
                    int rowg = sidx ? sidx[r] : r;
                    float* o = OUT + (size_t)rowg * D;
#pragma unroll
                    for (int nf = 0; nf < 8; nf++) {
                        int c = wn * 64 + nf * 8 + 2 * t4;
                        float2 bi = *(const float2*)(bm + c);
                        float2 val = make_float2(acc[ma][nf][rr * 2 + 0] + bi.x,
                                                 acc[ma][nf][rr * 2 + 1] + bi.y);
                        *(float2*)(o + c) = val;
                    }
                }
            }
        }
    }
}

// ---------------------------------------------------------------------------
// Attention v3: 2 queries per thread, chunked online softmax (16-key chunks,
// scores in registers). K/V rows read once per thread serve both queries.
// Chunk-swizzled K/V smem (8 heads -> 8 distinct 16B bank slots).
// ---------------------------------------------------------------------------
template <int L, int TPB>
__global__ __launch_bounds__(TPB)
void attn2(const float* __restrict__ Q, const float* __restrict__ K,
           const float* __restrict__ V, const int* __restrict__ ws,
           float* __restrict__ AO, int nw)
{
    constexpr int QS  = L / 2;          // query slots per window
    constexpr int TPW = QS * 8;         // threads per window
    constexpr int WPB = TPB / TPW;      // windows per block
    extern __shared__ float4 sm4[];
    const int tid = threadIdx.x;
    const int wl  = tid / TPW;
    const int w   = blockIdx.x * WPB + wl;
    float4* Ks = sm4 + (size_t)wl * (2 * L * 32);
    float4* Vs = Ks + L * 32;

    int t0 = 0, len = 0;
    if (w < nw) { t0 = ws[w]; len = ws[w + 1] - t0; }

    const int lt = tid - wl * TPW;
    for (int idx = lt; idx < len * 32; idx += TPW) {
        int j = idx >> 5, gg = idx & 31;
        int h = gg >> 2, p = gg & 3;
        Ks[j * 32 + (p * 8 + h)] = ((const float4*)K)[(size_t)(t0 + j) * 32 + gg];
        Vs[j * 32 + (p * 8 + h)] = ((const float4*)V)[(size_t)(t0 + j) * 32 + gg];
    }
    __syncthreads();

    const int qs = lt >> 3;
    const int h  = lt & 7;
    const int q0 = 2 * qs, q1 = 2 * qs + 1;
    if (w >= nw || q0 >= len) return;
    const bool v1 = (q1 < len);

    float4 qv0[4], qv1[4];
    {
        const float4* Qp0 = (const float4*)Q + (size_t)(t0 + q0) * 32 + h * 4;
        const float4* Qp1 = (const float4*)Q + (size_t)(t0 + (v1 ? q1 : q0)) * 32 + h * 4;
#pragma unroll
        for (int p = 0; p < 4; p++) { qv0[p] = Qp0[p]; qv1[p] = Qp1[p]; }
    }

    float m0 = -1e30f, m1 = -1e30f, d0 = 0.f, d1 = 0.f;
    float acc0[16], acc1[16];
#pragma unroll
    for (int e = 0; e < 16; e++) { acc0[e] = 0.f; acc1[e] = 0.f; }

    for (int c0 = 0; c0 < len; c0 += 16) {
        float s0[16], s1[16];
#pragma unroll
        for (int j = 0; j < 16; j++) {
            if (L > 16 && c0 + j >= len) { s0[j] = -1e30f; s1[j] = -1e30f; continue; }
            const float4* kr = Ks + (c0 + j) * 32 + h;
            float a = 0.f, b = 0.f;
#pragma unroll
            for (int p = 0; p < 4; p++) {
                float4 kk = kr[p * 8];
                a += qv0[p].x * kk.x + qv0[p].y * kk.y + qv0[p].z * kk.z + qv0[p].w * kk.w;
                b += qv1[p].x * kk.x + qv1[p].y * kk.y + qv1[p].z * kk.z + qv1[p].w * kk.w;
            }
            bool vk = (L <= 16) ? (c0 + j < len) : true;
            s0[j] = vk ? a : -1e30f;
            s1[j] = vk ? b : -1e30f;
        }
        float cm0 = s0[0], cm1 = s1[0];
#pragma unroll
        for (int j = 1; j < 16; j++) { cm0 = fmaxf(cm0, s0[j]); cm1 = fmaxf(cm1, s1[j]); }
        float mn0 = fmaxf(m0, cm0), mn1 = fmaxf(m1, cm1);
        float sc0 = __expf((m0 - mn0) * 0.25f);     // 0 on first chunk (m=-1e30)
        float sc1 = __expf((m1 - mn1) * 0.25f);
        m0 = mn0; m1 = mn1;
        d0 *= sc0; d1 *= sc1;
#pragma unroll
        for (int e = 0; e < 16; e++) { acc0[e] *= sc0; acc1[e] *= sc1; }

#pragma unroll
        for (int j = 0; j < 16; j++) {
            if (c0 + j >= len) break;
            float p0 = __expf((s0[j] - m0) * 0.25f);
            float p1 = __expf((s1[j] - m1) * 0.25f);
            d0 += p0; d1 += p1;
            const float4* vr = Vs + (c0 + j) * 32 + h;
#pragma unroll
            for (int p = 0; p < 4; p++) {
                float4 vv = vr[p * 8];
                acc0[p * 4 + 0] += p0 * vv.x;  acc1[p * 4 + 0] += p1 * vv.x;
                acc0[p * 4 + 1] += p0 * vv.y;  acc1[p * 4 + 1] += p1 * vv.y;
                acc0[p * 4 + 2] += p0 * vv.z;  acc1[p * 4 + 2] += p1 * vv.z;
                acc0[p * 4 + 3] += p0 * vv.w;  acc1[p * 4 + 3] += p1 * vv.w;
            }
        }
    }

    {
        float inv = 1.f / d0;
        float4* o = (float4*)(AO + (size_t)(t0 + q0) * D + h * 16);
#pragma unroll
        for (int p = 0; p < 4; p++)
            o[p] = make_float4(acc0[p * 4 + 0] * inv, acc0[p * 4 + 1] * inv,
                               acc0[p * 4 + 2] * inv, acc0[p * 4 + 3] * inv);
    }
    if (v1) {
        float inv = 1.f / d1;
        float4* o = (float4*)(AO + (size_t)(t0 + q1) * D + h * 16);
#pragma unroll
        for (int p = 0; p < 4; p++)
            o[p] = make_float4(acc1[p * 4 + 0] * inv, acc1[p * 4 + 1] * inv,
                               acc1[p * 4 + 2] * inv, acc1[p * 4 + 3] * inv);
    }
}

// ---------------------------------------------------------------------------
extern "C" void kernel_launch(void* const* d_in, const int* in_sizes, int n_in,
                              void* d_out, int out_size)
{
    const float* feat  = (const float*)d_in[0];
    const float* pos16 = (const float*)d_in[1];
    const float* pos64 = (const float*)d_in[2];
    const float* Win   = (const float*)d_in[3];
    const float* bin   = (const float*)d_in[4];
    const float* Wout  = (const float*)d_in[5];
    const float* bout  = (const float*)d_in[6];
    const int* vox16 = (const int*)d_in[7];
    const int* fp16  = (const int*)d_in[8];
    const int* vox64 = (const int*)d_in[9];
    const int* fp64  = (const int*)d_in[10];
    const int n16  = in_sizes[7];
    const int n64  = in_sizes[9];
    const int nw16 = in_sizes[1] / (16 * D);
    const int nw64 = in_sizes[2] / (64 * D);
    float* out = (float*)d_out;

    float* scr = nullptr;
    cudaGetSymbolAddress((void**)&scr, g_scr);
    int* ws16 = nullptr; cudaGetSymbolAddress((void**)&ws16, g_ws16);
    int* ws64 = nullptr; cudaGetSymbolAddress((void**)&ws64, g_ws64);
    float* Qb = scr;
    float* Kb = scr + (size_t)NMAX * D;
    float* Vb = scr + (size_t)2 * NMAX * D;
    float* AO = scr + (size_t)3 * NMAX * D;

    const size_t gsm   = 64 * SAK * sizeof(float);                  // 33792
    const size_t asm16 = (size_t)4 * 2 * 16 * 32 * sizeof(float4);  // 64 KB
    const size_t asm64 = (size_t)1 * 2 * 64 * 32 * sizeof(float4);  // 64 KB
    cudaFuncSetAttribute((const void*)attn2<16, 256>, cudaFuncAttributeMaxDynamicSharedMemorySize, (int)asm16);
    cudaFuncSetAttribute((const void*)attn2<64, 256>, cudaFuncAttributeMaxDynamicSharedMemorySize, (int)asm64);

    build_ws<<<(n16 + 255) / 256, 256>>>(fp16, n16, 16, ws16, nw16);
    build_ws<<<(n64 + 255) / 256, 256>>>(fp64, n64, 64, ws64, nw64);
    pack_w<<<128, 256>>>(Win, Wout);

    const int gb16 = (n16 + 63) / 64, gb64 = (n64 + 63) / 64;
    const size_t off = (size_t)n16 * D;

    // Fused Q+K projection (A staged once), V separate.  wmat: 0=Wq,1=Wk,2=Wv,3=Wout
    gemm_mma<true, 2><<<gb16, 128, gsm>>>(feat, vox16, pos16, fp16, 0, bin,
                                          Qb, Kb, nullptr, n16);
    gemm_mma<false, 1><<<gb16, 128, gsm>>>(feat, vox16, nullptr, nullptr, 2, bin + 256,
                                           Vb, nullptr, nullptr, n16);
    gemm_mma<true, 2><<<gb64, 128, gsm>>>(feat, vox64, pos64, fp64, 0, bin,
                                          Qb + off, Kb + off, nullptr, n64);
    gemm_mma<false, 1><<<gb64, 128, gsm>>>(feat, vox64, nullptr, nullptr, 2, bin + 256,
                                           Vb + off, nullptr, nullptr, n64);

    // Attention: 2 queries/thread, chunked online softmax
    attn2<16, 256><<<(nw16 + 3) / 4, 256, asm16>>>(Qb, Kb, Vb, ws16, AO, nw16);
    attn2<64, 256><<<nw64, 256, asm64>>>(Qb + off, Kb + off, Vb + off, ws64, AO + off, nw64);

    // Output projection, scattered straight into d_out
    gemm_mma<false, 1><<<gb16, 128, gsm>>>(AO, nullptr, nullptr, nullptr, 3, bout,
                                           out, nullptr, vox16, n16);
    gemm_mma<false, 1><<<gb64, 128, gsm>>>(AO + off, nullptr, nullptr, nullptr, 3, bout,
                                           out, nullptr, vox64, n64);
}

// round 8
// speedup vs baseline: 2.8346x; 1.0937x over previous
#include <cuda_runtime.h>
#include <math.h>

#define D 128
#define NMAX 210048
#define SAK 132   // As stride: (4g+t)%32 distinct per lane -> conflict-free frags

// Scratch: Q, K, V, attention-out  (~430 MB, static)
__device__ float g_scr[(size_t)4 * NMAX * D];
__device__ float g_wpack[4 * D * D];   // mma-fragment-packed weights (tf32)
__device__ int g_ws16[20002];
__device__ int g_ws64[8002];

__device__ __forceinline__ float to_tf32(float x) {
    asm("cvt.rna.tf32.f32 %0, %0;" : "+f"(x));
    return x;
}

// ---------------------------------------------------------------------------
// Window-start builder (flat_pos strictly increasing -> contiguous ranges).
// ---------------------------------------------------------------------------
__global__ void build_ws(const int* __restrict__ fp, int n, int L,
                         int* __restrict__ ws, int nw)
{
    int i = blockIdx.x * blockDim.x + threadIdx.x;
    if (i < n) {
        int w = fp[i] / L;
        if (i == 0 || fp[i - 1] / L != w) ws[w] = i;
    }
    if (i == 0) ws[nw] = n;
}

// ---------------------------------------------------------------------------
// Pack W into m16n8k8 B-fragment order, tf32-rounded.
//   g_wpack[m][ks][nf][lane] = float2( W[nf*8+g][ks*8+t], W[nf*8+g][ks*8+t+4] )
// ---------------------------------------------------------------------------
__global__ void pack_w(const float* __restrict__ Win, const float* __restrict__ Wout)
{
    int i = blockIdx.x * blockDim.x + threadIdx.x;   // 0..32767
    if (i >= 4 * 16 * 16 * 32) return;
    int lane = i & 31;
    int nf = (i >> 5) & 15;
    int ks = (i >> 9) & 15;
    int m  = i >> 13;
    int g = lane >> 2, t = lane & 3;
    const float* W = (m < 3) ? (Win + (size_t)m * D * D) : Wout;
    int row = nf * 8 + g;
    int col = ks * 8 + t;
    float w0 = to_tf32(W[row * D + col]);
    float w1 = to_tf32(W[row * D + col + 4]);
    ((float2*)g_wpack)[i] = make_float2(w0, w1);
}

// ---------------------------------------------------------------------------
// TF32 tensor-core GEMM, both ragged groups merged in one grid.
//   Block: 64 tokens x 128 channels, 256 threads = 8 warps, warp tile 32x32.
//   NM=3 (QKV): A staged twice from ONE gather — with pos (Q,K) and raw (V).
//   NM=1 (out-proj): single A tile, optional scatter epilogue.
//   B fragments read straight from L1/L2-resident g_wpack.
// ---------------------------------------------------------------------------
template <bool ADD_POS, int NM, bool GATHER, bool SCATTER>
__global__ __launch_bounds__(256, 3)
void gemm_mma(const float* __restrict__ X,
              const int* __restrict__ g16, const int* __restrict__ g64,
              const float* __restrict__ pos16, const float* __restrict__ pos64,
              const int* __restrict__ fp16, const int* __restrict__ fp64,
              int wmat, const float* __restrict__ bias,
              float* __restrict__ O0, float* __restrict__ O1, float* __restrict__ O2,
              const int* __restrict__ s16, const int* __restrict__ s64,
              int n16, int ntok)
{
    extern __shared__ float sm[];
    float* As = sm;                                   // pos-added tile (or only tile)
    float* Ar = (NM == 3) ? sm + 64 * SAK : sm;       // raw tile (V operand)
    const int tid = threadIdx.x;
    const int tb = blockIdx.x * 64;

    // Stage A: one gather serves both tiles
#pragma unroll
    for (int it = 0; it < 8; it++) {
        int idx = tid + it * 256;          // 0..2047 float4 slots
        int r  = idx >> 5;
        int c4 = (idx & 31) << 2;
        int tk = tb + r;
        float4 v = make_float4(0.f, 0.f, 0.f, 0.f);
        float4 vp = v;
        if (tk < ntok) {
            bool gA = tk < n16;
            int src = GATHER ? (gA ? g16[tk] : g64[tk - n16]) : tk;
            v = *(const float4*)(X + (size_t)src * D + c4);
            vp = v;
            if (ADD_POS) {
                const float* P = gA ? pos16 : pos64;
                int f = gA ? fp16[tk] : fp64[tk - n16];
                float4 p = *(const float4*)(P + (size_t)f * D + c4);
                vp.x += p.x; vp.y += p.y; vp.z += p.z; vp.w += p.w;
            }
        }
        As[r * SAK + c4 + 0] = to_tf32(vp.x);
        As[r * SAK + c4 + 1] = to_tf32(vp.y);
        As[r * SAK + c4 + 2] = to_tf32(vp.z);
        As[r * SAK + c4 + 3] = to_tf32(vp.w);
        if (NM == 3) {
            Ar[r * SAK + c4 + 0] = to_tf32(v.x);
            Ar[r * SAK + c4 + 1] = to_tf32(v.y);
            Ar[r * SAK + c4 + 2] = to_tf32(v.z);
            Ar[r * SAK + c4 + 3] = to_tf32(v.w);
        }
    }
    __syncthreads();

    const int w  = tid >> 5, lane = tid & 31;
    const int wm = w & 1,  wn = w >> 1;               // wm: 32-token half, wn: 32-col quarter
    const int g  = lane >> 2, t4 = lane & 3;

#pragma unroll
    for (int m = 0; m < NM; m++) {
        const unsigned* Asu = (const unsigned*)((NM == 3 && m == 2) ? Ar : As);
        float acc[2][4][4];
#pragma unroll
        for (int ma = 0; ma < 2; ma++)
#pragma unroll
            for (int nf = 0; nf < 4; nf++)
#pragma unroll
                for (int e = 0; e < 4; e++) acc[ma][nf][e] = 0.f;

        const unsigned* ap = Asu + (wm * 32 + g) * SAK + t4;
        const float2* bp = (const float2*)g_wpack
                         + ((size_t)(wmat + m) * 256) * 32 + (wn * 4) * 32 + lane;

#pragma unroll
        for (int ks = 0; ks < 16; ks++) {
            unsigned a[2][4];
#pragma unroll
            for (int ma = 0; ma < 2; ma++) {
                const unsigned* ar = ap + ma * 16 * SAK + ks * 8;
                a[ma][0] = ar[0];
                a[ma][1] = ar[8 * SAK];
                a[ma][2] = ar[4];
                a[ma][3] = ar[8 * SAK + 4];
            }
#pragma unroll
            for (int nf = 0; nf < 4; nf++) {
                float2 bv = __ldg(bp + (ks * 16 + nf) * 32);
                unsigned b0 = __float_as_uint(bv.x);
                unsigned b1 = __float_as_uint(bv.y);
#pragma unroll
                for (int ma = 0; ma < 2; ma++) {
                    asm volatile(
                        "mma.sync.aligned.m16n8k8.row.col.f32.tf32.tf32.f32 "
                        "{%0,%1,%2,%3}, {%4,%5,%6,%7}, {%8,%9}, {%0,%1,%2,%3};"
                        : "+f"(acc[ma][nf][0]), "+f"(acc[ma][nf][1]),
                          "+f"(acc[ma][nf][2]), "+f"(acc[ma][nf][3])
                        : "r"(a[ma][0]), "r"(a[ma][1]), "r"(a[ma][2]), "r"(a[ma][3]),
                          "r"(b0), "r"(b1));
                }
            }
        }

        // Epilogue: c0,c1 -> row g, cols 2t,2t+1; c2,c3 -> row g+8
        const float* bm = bias + m * D;
        float* OUT = (m == 0) ? O0 : (m == 1) ? O1 : O2;
#pragma unroll
        for (int ma = 0; ma < 2; ma++) {
#pragma unroll
            for (int rr = 0; rr < 2; rr++) {
                int r = tb + wm * 32 + ma * 16 + g + rr * 8;
                if (r < ntok) {
                    int rowg = r;
                    if (SCATTER) rowg = (r < n16) ? s16[r] : s64[r - n16];
                    float* o = OUT + (size_t)rowg * D;
#pragma unroll
                    for (int nf = 0; nf < 4; nf++) {
                        int c = wn * 32 + nf * 8 + 2 * t4;
                        float2 bi = *(const float2*)(bm + c);
                        float2 val = make_float2(acc[ma][nf][rr * 2 + 0] + bi.x,
                                                 acc[ma][nf][rr * 2 + 1] + bi.y);
                        *(float2*)(o + c) = val;
                    }
                }
            }
        }
    }
}

// ---------------------------------------------------------------------------
// Attention: 2 queries per thread, chunked online softmax (16-key chunks,
// scores in registers). Chunk-swizzled K/V smem (8 heads -> 8 bank slots).
// ---------------------------------------------------------------------------
template <int L, int TPB>
__global__ __launch_bounds__(TPB)
void attn2(const float* __restrict__ Q, const float* __restrict__ K,
           const float* __restrict__ V, const int* __restrict__ ws,
           float* __restrict__ AO, int nw)
{
    constexpr int QS  = L / 2;
    constexpr int TPW = QS * 8;
    constexpr int WPB = TPB / TPW;
    extern __shared__ float4 sm4[];
    const int tid = threadIdx.x;
    const int wl  = tid / TPW;
    const int w   = blockIdx.x * WPB + wl;
    float4* Ks = sm4 + (size_t)wl * (2 * L * 32);
    float4* Vs = Ks + L * 32;

    int t0 = 0, len = 0;
    if (w < nw) { t0 = ws[w]; len = ws[w + 1] - t0; }

    const int lt = tid - wl * TPW;
    for (int idx = lt; idx < len * 32; idx += TPW) {
        int j = idx >> 5, gg = idx & 31;
        int h = gg >> 2, p = gg & 3;
        Ks[j * 32 + (p * 8 + h)] = ((const float4*)K)[(size_t)(t0 + j) * 32 + gg];
        Vs[j * 32 + (p * 8 + h)] = ((const float4*)V)[(size_t)(t0 + j) * 32 + gg];
    }
    __syncthreads();

    const int qs = lt >> 3;
    const int h  = lt & 7;
    const int q0 = 2 * qs, q1 = 2 * qs + 1;
    if (w >= nw || q0 >= len) return;
    const bool v1 = (q1 < len);

    float4 qv0[4], qv1[4];
    {
        const float4* Qp0 = (const float4*)Q + (size_t)(t0 + q0) * 32 + h * 4;
        const float4* Qp1 = (const float4*)Q + (size_t)(t0 + (v1 ? q1 : q0)) * 32 + h * 4;
#pragma unroll
        for (int p = 0; p < 4; p++) { qv0[p] = Qp0[p]; qv1[p] = Qp1[p]; }
    }

    float m0 = -1e30f, m1 = -1e30f, d0 = 0.f, d1 = 0.f;
    float acc0[16], acc1[16];
#pragma unroll
    for (int e = 0; e < 16; e++) { acc0[e] = 0.f; acc1[e] = 0.f; }

    for (int c0 = 0; c0 < len; c0 += 16) {
        float s0[16], s1[16];
#pragma unroll
        for (int j = 0; j < 16; j++) {
            if (L > 16 && c0 + j >= len) { s0[j] = -1e30f; s1[j] = -1e30f; continue; }
            const float4* kr = Ks + (c0 + j) * 32 + h;
            float a = 0.f, b = 0.f;
#pragma unroll
            for (int p = 0; p < 4; p++) {
                float4 kk = kr[p * 8];
                a += qv0[p].x * kk.x + qv0[p].y * kk.y + qv0[p].z * kk.z + qv0[p].w * kk.w;
                b += qv1[p].x * kk.x + qv1[p].y * kk.y + qv1[p].z * kk.z + qv1[p].w * kk.w;
            }
            bool vk = (L <= 16) ? (c0 + j < len) : true;
            s0[j] = vk ? a : -1e30f;
            s1[j] = vk ? b : -1e30f;
        }
        float cm0 = s0[0], cm1 = s1[0];
#pragma unroll
        for (int j = 1; j < 16; j++) { cm0 = fmaxf(cm0, s0[j]); cm1 = fmaxf(cm1, s1[j]); }
        float mn0 = fmaxf(m0, cm0), mn1 = fmaxf(m1, cm1);
        float sc0 = __expf((m0 - mn0) * 0.25f);
        float sc1 = __expf((m1 - mn1) * 0.25f);
        m0 = mn0; m1 = mn1;
        d0 *= sc0; d1 *= sc1;
#pragma unroll
        for (int e = 0; e < 16; e++) { acc0[e] *= sc0; acc1[e] *= sc1; }

#pragma unroll
        for (int j = 0; j < 16; j++) {
            if (c0 + j >= len) break;
            float p0 = __expf((s0[j] - m0) * 0.25f);
            float p1 = __expf((s1[j] - m1) * 0.25f);
            d0 += p0; d1 += p1;
            const float4* vr = Vs + (c0 + j) * 32 + h;
#pragma unroll
            for (int p = 0; p < 4; p++) {
                float4 vv = vr[p * 8];
                acc0[p * 4 + 0] += p0 * vv.x;  acc1[p * 4 + 0] += p1 * vv.x;
                acc0[p * 4 + 1] += p0 * vv.y;  acc1[p * 4 + 1] += p1 * vv.y;
                acc0[p * 4 + 2] += p0 * vv.z;  acc1[p * 4 + 2] += p1 * vv.z;
                acc0[p * 4 + 3] += p0 * vv.w;  acc1[p * 4 + 3] += p1 * vv.w;
            }
        }
    }

    {
        float inv = 1.f / d0;
        float4* o = (float4*)(AO + (size_t)(t0 + q0) * D + h * 16);
#pragma unroll
        for (int p = 0; p < 4; p++)
            o[p] = make_float4(acc0[p * 4 + 0] * inv, acc0[p * 4 + 1] * inv,
                               acc0[p * 4 + 2] * inv, acc0[p * 4 + 3] * inv);
    }
    if (v1) {
        float inv = 1.f / d1;
        float4* o = (float4*)(AO + (size_t)(t0 + q1) * D + h * 16);
#pragma unroll
        for (int p = 0; p < 4; p++)
            o[p] = make_float4(acc1[p * 4 + 0] * inv, acc1[p * 4 + 1] * inv,
                               acc1[p * 4 + 2] * inv, acc1[p * 4 + 3] * inv);
    }
}

// ---------------------------------------------------------------------------
extern "C" void kernel_launch(void* const* d_in, const int* in_sizes, int n_in,
                              void* d_out, int out_size)
{
    const float* feat  = (const float*)d_in[0];
    const float* pos16 = (const float*)d_in[1];
    const float* pos64 = (const float*)d_in[2];
    const float* Win   = (const float*)d_in[3];
    const float* bin   = (const float*)d_in[4];
    const float* Wout  = (const float*)d_in[5];
    const float* bout  = (const float*)d_in[6];
    const int* vox16 = (const int*)d_in[7];
    const int* fp16  = (const int*)d_in[8];
    const int* vox64 = (const int*)d_in[9];
    const int* fp64  = (const int*)d_in[10];
    const int n16  = in_sizes[7];
    const int n64  = in_sizes[9];
    const int nw16 = in_sizes[1] / (16 * D);
    const int nw64 = in_sizes[2] / (64 * D);
    const int ntok = n16 + n64;
    float* out = (float*)d_out;

    float* scr = nullptr;
    cudaGetSymbolAddress((void**)&scr, g_scr);
    int* ws16 = nullptr; cudaGetSymbolAddress((void**)&ws16, g_ws16);
    int* ws64 = nullptr; cudaGetSymbolAddress((void**)&ws64, g_ws64);
    float* Qb = scr;
    float* Kb = scr + (size_t)NMAX * D;
    float* Vb = scr + (size_t)2 * NMAX * D;
    float* AO = scr + (size_t)3 * NMAX * D;

    const size_t ASZ   = (size_t)64 * SAK * sizeof(float);          // 33792
    const size_t gsm3  = 2 * ASZ;                                   // 67584 (QKV)
    const size_t asm16 = (size_t)4 * 2 * 16 * 32 * sizeof(float4);  // 64 KB
    const size_t asm64 = (size_t)1 * 2 * 64 * 32 * sizeof(float4);  // 64 KB
    cudaFuncSetAttribute((const void*)gemm_mma<true, 3, true, false>,
                         cudaFuncAttributeMaxDynamicSharedMemorySize, (int)gsm3);
    cudaFuncSetAttribute((const void*)gemm_mma<false, 1, false, true>,
                         cudaFuncAttributeMaxDynamicSharedMemorySize, (int)ASZ);
    cudaFuncSetAttribute((const void*)attn2<16, 256>, cudaFuncAttributeMaxDynamicSharedMemorySize, (int)asm16);
    cudaFuncSetAttribute((const void*)attn2<64, 256>, cudaFuncAttributeMaxDynamicSharedMemorySize, (int)asm64);

    build_ws<<<(n16 + 255) / 256, 256>>>(fp16, n16, 16, ws16, nw16);
    build_ws<<<(n64 + 255) / 256, 256>>>(fp64, n64, 64, ws64, nw64);
    pack_w<<<128, 256>>>(Win, Wout);

    const int gt = (ntok + 63) / 64;
    const size_t off = (size_t)n16 * D;

    // Fused Q+K+V over BOTH groups: one gather, three matrices.
    gemm_mma<true, 3, true, false><<<gt, 256, gsm3>>>(
        feat, vox16, vox64, pos16, pos64, fp16, fp64, 0, bin,
        Qb, Kb, Vb, nullptr, nullptr, n16, ntok);

    // Attention: 2 queries/thread, chunked online softmax
    attn2<16, 256><<<(nw16 + 3) / 4, 256, asm16>>>(Qb, Kb, Vb, ws16, AO, nw16);
    attn2<64, 256><<<nw64, 256, asm64>>>(Qb + off, Kb + off, Vb + off, ws64, AO + off, nw64);

    // Output projection over BOTH groups, scattered straight into d_out
    gemm_mma<false, 1, false, true><<<gt, 256, ASZ>>>(
        AO, nullptr, nullptr, nullptr, nullptr, nullptr, nullptr, 3, bout,
        out, nullptr, nullptr, vox16, vox64, n16, ntok);
}

// round 9
// speedup vs baseline: 3.0707x; 1.0833x over previous
#include <cuda_runtime.h>
#include <cuda_fp16.h>
#include <math.h>

#define D 128
#define NMAX 210048
#define SAH 68   // A-tile row stride in half2 units (272B); 68 % 32 == 4 -> conflict-free frags

// Scratch: Q, K, V, attention-out  (~430 MB, static)
__device__ float g_scr[(size_t)4 * NMAX * D];
__device__ uint2 g_wpackh[4 * 8 * 16 * 32];   // fp16 m16n8k16 B fragments, 32KB/matrix
__device__ int g_ws16[20002];
__device__ int g_ws64[8002];

// ---------------------------------------------------------------------------
// Window-start builder (flat_pos strictly increasing -> contiguous ranges).
// ---------------------------------------------------------------------------
__global__ void build_ws(const int* __restrict__ fp, int n, int L,
                         int* __restrict__ ws, int nw)
{
    int i = blockIdx.x * blockDim.x + threadIdx.x;
    if (i < n) {
        int w = fp[i] / L;
        if (i == 0 || fp[i - 1] / L != w) ws[w] = i;
    }
    if (i == 0) ws[nw] = n;
}

// ---------------------------------------------------------------------------
// Pack W into m16n8k16 fp16 B-fragment order.
//   b0 = {W[n][k0], W[n][k0+1]},  b1 = {W[n][k0+8], W[n][k0+9]}
//   with n = nf*8+g, k0 = ks*16 + 2*t4   (g = lane>>2, t4 = lane&3)
// ---------------------------------------------------------------------------
__global__ void pack_w(const float* __restrict__ Win, const float* __restrict__ Wout)
{
    int i = blockIdx.x * blockDim.x + threadIdx.x;   // 0..16383
    if (i >= 4 * 8 * 16 * 32) return;
    int lane = i & 31;
    int nf = (i >> 5) & 15;
    int ks = (i >> 9) & 7;
    int m  = i >> 12;
    int g = lane >> 2, t4 = lane & 3;
    const float* W = (m < 3) ? (Win + (size_t)m * D * D) : Wout;
    int n  = nf * 8 + g;
    int k0 = ks * 16 + 2 * t4;
    __half2 b0 = __floats2half2_rn(W[n * D + k0],     W[n * D + k0 + 1]);
    __half2 b1 = __floats2half2_rn(W[n * D + k0 + 8], W[n * D + k0 + 9]);
    uint2 out;
    out.x = *(unsigned*)&b0;
    out.y = *(unsigned*)&b1;
    g_wpackh[i] = out;
}

// ---------------------------------------------------------------------------
// FP16 tensor-core GEMM (m16n8k16, fp32 accum), both ragged groups in one grid.
//   Block: 64 tokens x 128 channels, 256 threads = 8 warps, warp tile 32x32.
//   NM=3 (QKV): two fp16 A tiles (pos-added, raw) from ONE gather.
//   NM=1 (out-proj): single tile, optional scatter epilogue.
//   B fragments from L1/L2-resident g_wpackh.
// ---------------------------------------------------------------------------
template <bool ADD_POS, int NM, bool GATHER, bool SCATTER>
__global__ __launch_bounds__(256, 4)
void gemm_mma(const float* __restrict__ X,
              const int* __restrict__ g16, const int* __restrict__ g64,
              const float* __restrict__ pos16, const float* __restrict__ pos64,
              const int* __restrict__ fp16x, const int* __restrict__ fp64x,
              int wmat, const float* __restrict__ bias,
              float* __restrict__ O0, float* __restrict__ O1, float* __restrict__ O2,
              const int* __restrict__ s16, const int* __restrict__ s64,
              int n16, int ntok)
{
    extern __shared__ unsigned smu[];                 // A tiles as half2 words
    unsigned* As = smu;                               // 64 x SAH  (pos-added / only)
    unsigned* Ar = (NM == 3) ? smu + 64 * SAH : smu;  // raw tile (V operand)
    const int tid = threadIdx.x;
    const int tb = blockIdx.x * 64;

    // Stage A: one gather serves both fp16 tiles
#pragma unroll
    for (int it = 0; it < 8; it++) {
        int idx = tid + it * 256;          // 0..2047 float4 slots
        int r  = idx >> 5;
        int c4 = (idx & 31) << 2;          // fp32 col 0,4,...,124
        int tk = tb + r;
        float4 v = make_float4(0.f, 0.f, 0.f, 0.f);
        float4 vp = v;
        if (tk < ntok) {
            bool gA = tk < n16;
            int src = GATHER ? (gA ? g16[tk] : g64[tk - n16]) : tk;
            v = *(const float4*)(X + (size_t)src * D + c4);
            vp = v;
            if (ADD_POS) {
                const float* P = gA ? pos16 : pos64;
                int f = gA ? fp16x[tk] : fp64x[tk - n16];
                float4 p = *(const float4*)(P + (size_t)f * D + c4);
                vp.x += p.x; vp.y += p.y; vp.z += p.z; vp.w += p.w;
            }
        }
        int wi = r * SAH + (c4 >> 1);      // half2 word index, 8B aligned
        {
            __half2 h0 = __floats2half2_rn(vp.x, vp.y);
            __half2 h1 = __floats2half2_rn(vp.z, vp.w);
            uint2 st; st.x = *(unsigned*)&h0; st.y = *(unsigned*)&h1;
            *(uint2*)(As + wi) = st;
        }
        if (NM == 3) {
            __half2 h0 = __floats2half2_rn(v.x, v.y);
            __half2 h1 = __floats2half2_rn(v.z, v.w);
            uint2 st; st.x = *(unsigned*)&h0; st.y = *(unsigned*)&h1;
            *(uint2*)(Ar + wi) = st;
        }
    }
    __syncthreads();

    const int w  = tid >> 5, lane = tid & 31;
    const int wm = w & 1,  wn = w >> 1;               // wm: 32-token half, wn: 32-col quarter
    const int g  = lane >> 2, t4 = lane & 3;

#pragma unroll
    for (int m = 0; m < NM; m++) {
        const unsigned* Asu = (NM == 3 && m == 2) ? Ar : As;
        float acc[2][4][4];
#pragma unroll
        for (int ma = 0; ma < 2; ma++)
#pragma unroll
            for (int nf = 0; nf < 4; nf++)
#pragma unroll
                for (int e = 0; e < 4; e++) acc[ma][nf][e] = 0.f;

        // a-frag base: row wm*32+g, k-word t4
        const unsigned* ap = Asu + (wm * 32 + g) * SAH + t4;
        // B fragments: matrix base + n-quarter (wn*4 nf slots)
        const uint2* bp = g_wpackh + ((size_t)(wmat + m) * 8 * 16 + wn * 4) * 32 + lane;

#pragma unroll
        for (int ks = 0; ks < 8; ks++) {
            unsigned a[2][4];
#pragma unroll
            for (int ma = 0; ma < 2; ma++) {
                const unsigned* ar = ap + ma * 16 * SAH + ks * 8;
                a[ma][0] = ar[0];              // A[row][k0,k0+1]
                a[ma][1] = ar[8 * SAH];        // A[row+8][k0,k0+1]
                a[ma][2] = ar[4];              // A[row][k0+8,k0+9]
                a[ma][3] = ar[8 * SAH + 4];    // A[row+8][k0+8,k0+9]
            }
#pragma unroll
            for (int nf = 0; nf < 4; nf++) {
                uint2 bv = __ldg(bp + (ks * 16 + nf) * 32);
#pragma unroll
                for (int ma = 0; ma < 2; ma++) {
                    asm volatile(
                        "mma.sync.aligned.m16n8k16.row.col.f32.f16.f16.f32 "
                        "{%0,%1,%2,%3}, {%4,%5,%6,%7}, {%8,%9}, {%0,%1,%2,%3};"
                        : "+f"(acc[ma][nf][0]), "+f"(acc[ma][nf][1]),
                          "+f"(acc[ma][nf][2]), "+f"(acc[ma][nf][3])
                        : "r"(a[ma][0]), "r"(a[ma][1]), "r"(a[ma][2]), "r"(a[ma][3]),
                          "r"(bv.x), "r"(bv.y));
                }
            }
        }

        // Epilogue: c0,c1 -> row g, cols 2t4,2t4+1; c2,c3 -> row g+8
        const float* bm = bias + m * D;
        float* OUT = (m == 0) ? O0 : (m == 1) ? O1 : O2;
#pragma unroll
        for (int ma = 0; ma < 2; ma++) {
#pragma unroll
            for (int rr = 0; rr < 2; rr++) {
                int r = tb + wm * 32 + ma * 16 + g + rr * 8;
                if (r < ntok) {
                    int rowg = r;
                    if (SCATTER) rowg = (r < n16) ? s16[r] : s64[r - n16];
                    float* o = OUT + (size_t)rowg * D;
#pragma unroll
                    for (int nf = 0; nf < 4; nf++) {
                        int c = wn * 32 + nf * 8 + 2 * t4;
                        float2 bi = *(const float2*)(bm + c);
                        float2 val = make_float2(acc[ma][nf][rr * 2 + 0] + bi.x,
                                                 acc[ma][nf][rr * 2 + 1] + bi.y);
                        *(float2*)(o + c) = val;
                    }
                }
            }
        }
    }
}

// ---------------------------------------------------------------------------
// Attention: 2 queries per thread, chunked online softmax (16-key chunks,
// scores in registers). Chunk-swizzled K/V smem (8 heads -> 8 bank slots).
// ---------------------------------------------------------------------------
template <int L, int TPB>
__global__ __launch_bounds__(TPB)
void attn2(const float* __restrict__ Q, const float* __restrict__ K,
           const float* __restrict__ V, const int* __restrict__ ws,
           float* __restrict__ AO, int nw)
{
    constexpr int QS  = L / 2;
    constexpr int TPW = QS * 8;
    constexpr int WPB = TPB / TPW;
    extern __shared__ float4 sm4[];
    const int tid = threadIdx.x;
    const int wl  = tid / TPW;
    const int w   = blockIdx.x * WPB + wl;
    float4* Ks = sm4 + (size_t)wl * (2 * L * 32);
    float4* Vs = Ks + L * 32;

    int t0 = 0, len = 0;
    if (w < nw) { t0 = ws[w]; len = ws[w + 1] - t0; }

    const int lt = tid - wl * TPW;
    for (int idx = lt; idx < len * 32; idx += TPW) {
        int j = idx >> 5, gg = idx & 31;
        int h = gg >> 2, p = gg & 3;
        Ks[j * 32 + (p * 8 + h)] = ((const float4*)K)[(size_t)(t0 + j) * 32 + gg];
        Vs[j * 32 + (p * 8 + h)] = ((const float4*)V)[(size_t)(t0 + j) * 32 + gg];
    }
    __syncthreads();

    const int qs = lt >> 3;
    const int h  = lt & 7;
    const int q0 = 2 * qs, q1 = 2 * qs + 1;
    if (w >= nw || q0 >= len) return;
    const bool v1 = (q1 < len);

    float4 qv0[4], qv1[4];
    {
        const float4* Qp0 = (const float4*)Q + (size_t)(t0 + q0) * 32 + h * 4;
        const float4* Qp1 = (const float4*)Q + (size_t)(t0 + (v1 ? q1 : q0)) * 32 + h * 4;
#pragma unroll
        for (int p = 0; p < 4; p++) { qv0[p] = Qp0[p]; qv1[p] = Qp1[p]; }
    }

    float m0 = -1e30f, m1 = -1e30f, d0 = 0.f, d1 = 0.f;
    float acc0[16], acc1[16];
#pragma unroll
    for (int e = 0; e < 16; e++) { acc0[e] = 0.f; acc1[e] = 0.f; }

    for (int c0 = 0; c0 < len; c0 += 16) {
        float s0[16], s1[16];
#pragma unroll
        for (int j = 0; j < 16; j++) {
            if (L > 16 && c0 + j >= len) { s0[j] = -1e30f; s1[j] = -1e30f; continue; }
            const float4* kr = Ks + (c0 + j) * 32 + h;
            float a = 0.f, b = 0.f;
#pragma unroll
            for (int p = 0; p < 4; p++) {
                float4 kk = kr[p * 8];
                a += qv0[p].x * kk.x + qv0[p].y * kk.y + qv0[p].z * kk.z + qv0[p].w * kk.w;
                b += qv1[p].x * kk.x + qv1[p].y * kk.y + qv1[p].z * kk.z + qv1[p].w * kk.w;
            }
            bool vk = (L <= 16) ? (c0 + j < len) : true;
            s0[j] = vk ? a : -1e30f;
            s1[j] = vk ? b : -1e30f;
        }
        float cm0 = s0[0], cm1 = s1[0];
#pragma unroll
        for (int j = 1; j < 16; j++) { cm0 = fmaxf(cm0, s0[j]); cm1 = fmaxf(cm1, s1[j]); }
        float mn0 = fmaxf(m0, cm0), mn1 = fmaxf(m1, cm1);
        float sc0 = __expf((m0 - mn0) * 0.25f);
        float sc1 = __expf((m1 - mn1) * 0.25f);
        m0 = mn0; m1 = mn1;
        d0 *= sc0; d1 *= sc1;
#pragma unroll
        for (int e = 0; e < 16; e++) { acc0[e] *= sc0; acc1[e] *= sc1; }

#pragma unroll
        for (int j = 0; j < 16; j++) {
            if (c0 + j >= len) break;
            float p0 = __expf((s0[j] - m0) * 0.25f);
            float p1 = __expf((s1[j] - m1) * 0.25f);
            d0 += p0; d1 += p1;
            const float4* vr = Vs + (c0 + j) * 32 + h;
#pragma unroll
            for (int p = 0; p < 4; p++) {
                float4 vv = vr[p * 8];
                acc0[p * 4 + 0] += p0 * vv.x;  acc1[p * 4 + 0] += p1 * vv.x;
                acc0[p * 4 + 1] += p0 * vv.y;  acc1[p * 4 + 1] += p1 * vv.y;
                acc0[p * 4 + 2] += p0 * vv.z;  acc1[p * 4 + 2] += p1 * vv.z;
                acc0[p * 4 + 3] += p0 * vv.w;  acc1[p * 4 + 3] += p1 * vv.w;
            }
        }
    }

    {
        float inv = 1.f / d0;
        float4* o = (float4*)(AO + (size_t)(t0 + q0) * D + h * 16);
#pragma unroll
        for (int p = 0; p < 4; p++)
            o[p] = make_float4(acc0[p * 4 + 0] * inv, acc0[p * 4 + 1] * inv,
                               acc0[p * 4 + 2] * inv, acc0[p * 4 + 3] * inv);
    }
    if (v1) {
        float inv = 1.f / d1;
        float4* o = (float4*)(AO + (size_t)(t0 + q1) * D + h * 16);
#pragma unroll
        for (int p = 0; p < 4; p++)
            o[p] = make_float4(acc1[p * 4 + 0] * inv, acc1[p * 4 + 1] * inv,
                               acc1[p * 4 + 2] * inv, acc1[p * 4 + 3] * inv);
    }
}

// ---------------------------------------------------------------------------
extern "C" void kernel_launch(void* const* d_in, const int* in_sizes, int n_in,
                              void* d_out, int out_size)
{
    const float* feat  = (const float*)d_in[0];
    const float* pos16 = (const float*)d_in[1];
    const float* pos64 = (const float*)d_in[2];
    const float* Win   = (const float*)d_in[3];
    const float* bin   = (const float*)d_in[4];
    const float* Wout  = (const float*)d_in[5];
    const float* bout  = (const float*)d_in[6];
    const int* vox16 = (const int*)d_in[7];
    const int* fp16i = (const int*)d_in[8];
    const int* vox64 = (const int*)d_in[9];
    const int* fp64i = (const int*)d_in[10];
    const int n16  = in_sizes[7];
    const int n64  = in_sizes[9];
    const int nw16 = in_sizes[1] / (16 * D);
    const int nw64 = in_sizes[2] / (64 * D);
    const int ntok = n16 + n64;
    float* out = (float*)d_out;

    float* scr = nullptr;
    cudaGetSymbolAddress((void**)&scr, g_scr);
    int* ws16 = nullptr; cudaGetSymbolAddress((void**)&ws16, g_ws16);
    int* ws64 = nullptr; cudaGetSymbolAddress((void**)&ws64, g_ws64);
    float* Qb = scr;
    float* Kb = scr + (size_t)NMAX * D;
    float* Vb = scr + (size_t)2 * NMAX * D;
    float* AO = scr + (size_t)3 * NMAX * D;

    const size_t ASZ   = (size_t)64 * SAH * sizeof(unsigned);       // 17408
    const size_t gsm3  = 2 * ASZ;                                   // 34816 (QKV)
    const size_t asm16 = (size_t)4 * 2 * 16 * 32 * sizeof(float4);  // 64 KB
    const size_t asm64 = (size_t)1 * 2 * 64 * 32 * sizeof(float4);  // 64 KB
    cudaFuncSetAttribute((const void*)gemm_mma<true, 3, true, false>,
                         cudaFuncAttributeMaxDynamicSharedMemorySize, (int)gsm3);
    cudaFuncSetAttribute((const void*)gemm_mma<false, 1, false, true>,
                         cudaFuncAttributeMaxDynamicSharedMemorySize, (int)ASZ);
    cudaFuncSetAttribute((const void*)attn2<16, 256>, cudaFuncAttributeMaxDynamicSharedMemorySize, (int)asm16);
    cudaFuncSetAttribute((const void*)attn2<64, 256>, cudaFuncAttributeMaxDynamicSharedMemorySize, (int)asm64);

    build_ws<<<(n16 + 255) / 256, 256>>>(fp16i, n16, 16, ws16, nw16);
    build_ws<<<(n64 + 255) / 256, 256>>>(fp64i, n64, 64, ws64, nw64);
    pack_w<<<64, 256>>>(Win, Wout);

    const int gt = (ntok + 63) / 64;
    const size_t off = (size_t)n16 * D;

    // Fused Q+K+V over BOTH groups: one gather, three matrices.
    gemm_mma<true, 3, true, false><<<gt, 256, gsm3>>>(
        feat, vox16, vox64, pos16, pos64, fp16i, fp64i, 0, bin,
        Qb, Kb, Vb, nullptr, nullptr, n16, ntok);

    // Attention: 2 queries/thread, chunked online softmax
    attn2<16, 256><<<(nw16 + 3) / 4, 256, asm16>>>(Qb, Kb, Vb, ws16, AO, nw16);
    attn2<64, 256><<<nw64, 256, asm64>>>(Qb + off, Kb + off, Vb + off, ws64, AO + off, nw64);

    // Output projection over BOTH groups, scattered straight into d_out
    gemm_mma<false, 1, false, true><<<gt, 256, ASZ>>>(
        AO, nullptr, nullptr, nullptr, nullptr, nullptr, nullptr, 3, bout,
        out, nullptr, nullptr, vox16, vox64, n16, ntok);
}

// round 10
// speedup vs baseline: 3.7250x; 1.2131x over previous
#include <cuda_runtime.h>
#include <cuda_fp16.h>
#include <math.h>

#define D 128
#define NMAX 210048
#define SAH 68   // A-tile row stride in half2 units (272B); 68 % 32 == 4 -> conflict-free frags

// Scratch: Q, K, V, attention-out in fp16 (~215 MB used of static pool)
__device__ float g_scr[(size_t)4 * NMAX * D / 2 + 1024];
__device__ uint2 g_wpackh[4 * 8 * 16 * 32];   // fp16 m16n8k16 B fragments, 32KB/matrix
__device__ int g_ws16[20002];
__device__ int g_ws64[8002];

// ---------------------------------------------------------------------------
__global__ void build_ws(const int* __restrict__ fp, int n, int L,
                         int* __restrict__ ws, int nw)
{
    int i = blockIdx.x * blockDim.x + threadIdx.x;
    if (i < n) {
        int w = fp[i] / L;
        if (i == 0 || fp[i - 1] / L != w) ws[w] = i;
    }
    if (i == 0) ws[nw] = n;
}

// ---------------------------------------------------------------------------
// Pack W into m16n8k16 fp16 B-fragment order.
// ---------------------------------------------------------------------------
__global__ void pack_w(const float* __restrict__ Win, const float* __restrict__ Wout)
{
    int i = blockIdx.x * blockDim.x + threadIdx.x;   // 0..16383
    if (i >= 4 * 8 * 16 * 32) return;
    int lane = i & 31;
    int nf = (i >> 5) & 15;
    int ks = (i >> 9) & 7;
    int m  = i >> 12;
    int g = lane >> 2, t4 = lane & 3;
    const float* W = (m < 3) ? (Win + (size_t)m * D * D) : Wout;
    int n  = nf * 8 + g;
    int k0 = ks * 16 + 2 * t4;
    __half2 b0 = __floats2half2_rn(W[n * D + k0],     W[n * D + k0 + 1]);
    __half2 b1 = __floats2half2_rn(W[n * D + k0 + 8], W[n * D + k0 + 9]);
    uint2 out;
    out.x = *(unsigned*)&b0;
    out.y = *(unsigned*)&b1;
    g_wpackh[i] = out;
}

// ---------------------------------------------------------------------------
// FP16 tensor-core GEMM (m16n8k16, fp32 accum), both ragged groups in one grid.
//   HIN:  A source is fp16 (AO) -> raw half2 copy into smem.
//   HOUT: outputs stored fp16 (Q/K/V); else fp32 (final output).
// ---------------------------------------------------------------------------
template <bool ADD_POS, int NM, bool GATHER, bool SCATTER, bool HIN, bool HOUT>
__global__ __launch_bounds__(256, 4)
void gemm_mma(const void* __restrict__ Xv,
              const int* __restrict__ g16, const int* __restrict__ g64,
              const float* __restrict__ pos16, const float* __restrict__ pos64,
              const int* __restrict__ fp16x, const int* __restrict__ fp64x,
              int wmat, const float* __restrict__ bias,
              void* __restrict__ O0, void* __restrict__ O1, void* __restrict__ O2,
              const int* __restrict__ s16, const int* __restrict__ s64,
              int n16, int ntok)
{
    extern __shared__ unsigned smu[];                 // A tiles as half2 words
    unsigned* As = smu;                               // 64 x SAH  (pos-added / only)
    unsigned* Ar = (NM == 3) ? smu + 64 * SAH : smu;  // raw tile (V operand)
    const int tid = threadIdx.x;
    const int tb = blockIdx.x * 64;

    // Stage A
#pragma unroll
    for (int it = 0; it < 8; it++) {
        int idx = tid + it * 256;          // 0..2047 (4-col slots)
        int r  = idx >> 5;
        int c4 = (idx & 31) << 2;          // col 0,4,...,124
        int tk = tb + r;
        int wi = r * SAH + (c4 >> 1);      // half2 word index, 8B aligned
        if (HIN) {
            uint2 st = make_uint2(0u, 0u);
            if (tk < ntok) {
                const unsigned* Xh = (const unsigned*)Xv;     // half2 words, 64/row
                st = *(const uint2*)(Xh + (size_t)tk * 64 + (c4 >> 1));
            }
            *(uint2*)(As + wi) = st;
        } else {
            const float* X = (const float*)Xv;
            float4 v = make_float4(0.f, 0.f, 0.f, 0.f);
            float4 vp = v;
            if (tk < ntok) {
                bool gA = tk < n16;
                int src = GATHER ? (gA ? g16[tk] : g64[tk - n16]) : tk;
                v = *(const float4*)(X + (size_t)src * D + c4);
                vp = v;
                if (ADD_POS) {
                    const float* P = gA ? pos16 : pos64;
                    int f = gA ? fp16x[tk] : fp64x[tk - n16];
                    float4 p = *(const float4*)(P + (size_t)f * D + c4);
                    vp.x += p.x; vp.y += p.y; vp.z += p.z; vp.w += p.w;
                }
            }
            {
                __half2 h0 = __floats2half2_rn(vp.x, vp.y);
                __half2 h1 = __floats2half2_rn(vp.z, vp.w);
                uint2 st; st.x = *(unsigned*)&h0; st.y = *(unsigned*)&h1;
                *(uint2*)(As + wi) = st;
            }
            if (NM == 3) {
                __half2 h0 = __floats2half2_rn(v.x, v.y);
                __half2 h1 = __floats2half2_rn(v.z, v.w);
                uint2 st; st.x = *(unsigned*)&h0; st.y = *(unsigned*)&h1;
                *(uint2*)(Ar + wi) = st;
            }
        }
    }
    __syncthreads();

    const int w  = tid >> 5, lane = tid & 31;
    const int wm = w & 1,  wn = w >> 1;
    const int g  = lane >> 2, t4 = lane & 3;

#pragma unroll
    for (int m = 0; m < NM; m++) {
        const unsigned* Asu = (NM == 3 && m == 2) ? Ar : As;
        float acc[2][4][4];
#pragma unroll
        for (int ma = 0; ma < 2; ma++)
#pragma unroll
            for (int nf = 0; nf < 4; nf++)
#pragma unroll
                for (int e = 0; e < 4; e++) acc[ma][nf][e] = 0.f;

        const unsigned* ap = Asu + (wm * 32 + g) * SAH + t4;
        const uint2* bp = g_wpackh + ((size_t)(wmat + m) * 8 * 16 + wn * 4) * 32 + lane;

#pragma unroll
        for (int ks = 0; ks < 8; ks++) {
            unsigned a[2][4];
#pragma unroll
            for (int ma = 0; ma < 2; ma++) {
                const unsigned* ar = ap + ma * 16 * SAH + ks * 8;
                a[ma][0] = ar[0];
                a[ma][1] = ar[8 * SAH];
                a[ma][2] = ar[4];
                a[ma][3] = ar[8 * SAH + 4];
            }
#pragma unroll
            for (int nf = 0; nf < 4; nf++) {
                uint2 bv = __ldg(bp + (ks * 16 + nf) * 32);
#pragma unroll
                for (int ma = 0; ma < 2; ma++) {
                    asm volatile(
                        "mma.sync.aligned.m16n8k16.row.col.f32.f16.f16.f32 "
                        "{%0,%1,%2,%3}, {%4,%5,%6,%7}, {%8,%9}, {%0,%1,%2,%3};"
                        : "+f"(acc[ma][nf][0]), "+f"(acc[ma][nf][1]),
                          "+f"(acc[ma][nf][2]), "+f"(acc[ma][nf][3])
                        : "r"(a[ma][0]), "r"(a[ma][1]), "r"(a[ma][2]), "r"(a[ma][3]),
                          "r"(bv.x), "r"(bv.y));
                }
            }
        }

        const float* bm = bias + m * D;
        void* OUT = (m == 0) ? O0 : (m == 1) ? O1 : O2;
#pragma unroll
        for (int ma = 0; ma < 2; ma++) {
#pragma unroll
            for (int rr = 0; rr < 2; rr++) {
                int r = tb + wm * 32 + ma * 16 + g + rr * 8;
                if (r < ntok) {
                    int rowg = r;
                    if (SCATTER) rowg = (r < n16) ? s16[r] : s64[r - n16];
#pragma unroll
                    for (int nf = 0; nf < 4; nf++) {
                        int c = wn * 32 + nf * 8 + 2 * t4;
                        float2 bi = *(const float2*)(bm + c);
                        float vx = acc[ma][nf][rr * 2 + 0] + bi.x;
                        float vy = acc[ma][nf][rr * 2 + 1] + bi.y;
                        if (HOUT) {
                            __half* o = (__half*)OUT + (size_t)rowg * D;
                            *(__half2*)(o + c) = __floats2half2_rn(vx, vy);
                        } else {
                            float* o = (float*)OUT + (size_t)rowg * D;
                            *(float2*)(o + c) = make_float2(vx, vy);
                        }
                    }
                }
            }
        }
    }
}

// ---------------------------------------------------------------------------
// Attention, fp16 I/O: 2 queries/thread, chunked online softmax.
//   K/V rows in smem as uint4 (8 halves) chunks, swizzled: head h chunk p
//   stored at slot p*8+h -> 8 heads hit 8 distinct 16B slots.
// ---------------------------------------------------------------------------
__device__ __forceinline__ void h8_to_f(const uint4& u, float* f) {
    float2 a = __half22float2(*(const __half2*)&u.x); f[0] = a.x; f[1] = a.y;
    float2 b = __half22float2(*(const __half2*)&u.y); f[2] = b.x; f[3] = b.y;
    float2 c = __half22float2(*(const __half2*)&u.z); f[4] = c.x; f[5] = c.y;
    float2 d = __half22float2(*(const __half2*)&u.w); f[6] = d.x; f[7] = d.y;
}

template <int L, int TPB>
__global__ __launch_bounds__(TPB)
void attn2(const __half* __restrict__ Q, const __half* __restrict__ K,
           const __half* __restrict__ V, const int* __restrict__ ws,
           __half* __restrict__ AO, int nw)
{
    constexpr int QS  = L / 2;
    constexpr int TPW = QS * 8;
    constexpr int WPB = TPB / TPW;
    extern __shared__ uint4 smh[];          // per window: 2 * L * 16 uint4
    const int tid = threadIdx.x;
    const int wl  = tid / TPW;
    const int w   = blockIdx.x * WPB + wl;
    uint4* Ks = smh + (size_t)wl * (2 * L * 16);
    uint4* Vs = Ks + L * 16;

    int t0 = 0, len = 0;
    if (w < nw) { t0 = ws[w]; len = ws[w + 1] - t0; }

    const int lt = tid - wl * TPW;
    for (int idx = lt; idx < len * 16; idx += TPW) {
        int j = idx >> 4, gg = idx & 15;     // gg: uint4 chunk in row (8 halves)
        int h = gg >> 1, p = gg & 1;
        Ks[j * 16 + (p * 8 + h)] = ((const uint4*)K)[(size_t)(t0 + j) * 16 + gg];
        Vs[j * 16 + (p * 8 + h)] = ((const uint4*)V)[(size_t)(t0 + j) * 16 + gg];
    }
    __syncthreads();

    const int qs = lt >> 3;
    const int h  = lt & 7;
    const int q0 = 2 * qs, q1 = 2 * qs + 1;
    if (w >= nw || q0 >= len) return;
    const bool v1 = (q1 < len);

    float qv0[16], qv1[16];
    {
        const uint4* Qp0 = (const uint4*)Q + (size_t)(t0 + q0) * 16 + h * 2;
        const uint4* Qp1 = (const uint4*)Q + (size_t)(t0 + (v1 ? q1 : q0)) * 16 + h * 2;
        h8_to_f(Qp0[0], qv0); h8_to_f(Qp0[1], qv0 + 8);
        h8_to_f(Qp1[0], qv1); h8_to_f(Qp1[1], qv1 + 8);
    }

    float m0 = -1e30f, m1 = -1e30f, d0 = 0.f, d1 = 0.f;
    float acc0[16], acc1[16];
#pragma unroll
    for (int e = 0; e < 16; e++) { acc0[e] = 0.f; acc1[e] = 0.f; }

    for (int c0 = 0; c0 < len; c0 += 16) {
        float s0[16], s1[16];
#pragma unroll
        for (int j = 0; j < 16; j++) {
            if (L > 16 && c0 + j >= len) { s0[j] = -1e30f; s1[j] = -1e30f; continue; }
            const uint4* kr = Ks + (c0 + j) * 16;
            float kf[16];
            h8_to_f(kr[h], kf); h8_to_f(kr[8 + h], kf + 8);
            float a = 0.f, b = 0.f;
#pragma unroll
            for (int d = 0; d < 16; d++) {
                a += qv0[d] * kf[d];
                b += qv1[d] * kf[d];
            }
            bool vk = (L <= 16) ? (c0 + j < len) : true;
            s0[j] = vk ? a : -1e30f;
            s1[j] = vk ? b : -1e30f;
        }
        float cm0 = s0[0], cm1 = s1[0];
#pragma unroll
        for (int j = 1; j < 16; j++) { cm0 = fmaxf(cm0, s0[j]); cm1 = fmaxf(cm1, s1[j]); }
        float mn0 = fmaxf(m0, cm0), mn1 = fmaxf(m1, cm1);
        float sc0 = __expf((m0 - mn0) * 0.25f);
        float sc1 = __expf((m1 - mn1) * 0.25f);
        m0 = mn0; m1 = mn1;
        d0 *= sc0; d1 *= sc1;
#pragma unroll
        for (int e = 0; e < 16; e++) { acc0[e] *= sc0; acc1[e] *= sc1; }

#pragma unroll
        for (int j = 0; j < 16; j++) {
            if (c0 + j >= len) break;
            float p0 = __expf((s0[j] - m0) * 0.25f);
            float p1 = __expf((s1[j] - m1) * 0.25f);
            d0 += p0; d1 += p1;
            const uint4* vr = Vs + (c0 + j) * 16;
            float vf[16];
            h8_to_f(vr[h], vf); h8_to_f(vr[8 + h], vf + 8);
#pragma unroll
            for (int e = 0; e < 16; e++) {
                acc0[e] += p0 * vf[e];
                acc1[e] += p1 * vf[e];
            }
        }
    }

    {
        float inv = 1.f / d0;
        __half2* o = (__half2*)(AO + (size_t)(t0 + q0) * D + h * 16);
#pragma unroll
        for (int e = 0; e < 8; e++)
            o[e] = __floats2half2_rn(acc0[2 * e] * inv, acc0[2 * e + 1] * inv);
    }
    if (v1) {
        float inv = 1.f / d1;
        __half2* o = (__half2*)(AO + (size_t)(t0 + q1) * D + h * 16);
#pragma unroll
        for (int e = 0; e < 8; e++)
            o[e] = __floats2half2_rn(acc1[2 * e] * inv, acc1[2 * e + 1] * inv);
    }
}

// ---------------------------------------------------------------------------
extern "C" void kernel_launch(void* const* d_in, const int* in_sizes, int n_in,
                              void* d_out, int out_size)
{
    const float* feat  = (const float*)d_in[0];
    const float* pos16 = (const float*)d_in[1];
    const float* pos64 = (const float*)d_in[2];
    const float* Win   = (const float*)d_in[3];
    const float* bin   = (const float*)d_in[4];
    const float* Wout  = (const float*)d_in[5];
    const float* bout  = (const float*)d_in[6];
    const int* vox16 = (const int*)d_in[7];
    const int* fp16i = (const int*)d_in[8];
    const int* vox64 = (const int*)d_in[9];
    const int* fp64i = (const int*)d_in[10];
    const int n16  = in_sizes[7];
    const int n64  = in_sizes[9];
    const int nw16 = in_sizes[1] / (16 * D);
    const int nw64 = in_sizes[2] / (64 * D);
    const int ntok = n16 + n64;
    float* out = (float*)d_out;

    float* scr = nullptr;
    cudaGetSymbolAddress((void**)&scr, g_scr);
    int* ws16 = nullptr; cudaGetSymbolAddress((void**)&ws16, g_ws16);
    int* ws64 = nullptr; cudaGetSymbolAddress((void**)&ws64, g_ws64);
    __half* Qh = (__half*)scr;
    __half* Kh = Qh + (size_t)NMAX * D;
    __half* Vh = Qh + (size_t)2 * NMAX * D;
    __half* AO = Qh + (size_t)3 * NMAX * D;

    const size_t ASZ   = (size_t)64 * SAH * sizeof(unsigned);       // 17408
    const size_t gsm3  = 2 * ASZ;                                   // 34816 (QKV)
    const size_t asm16 = (size_t)4 * 2 * 16 * 16 * sizeof(uint4);   // 32 KB
    const size_t asm64 = (size_t)1 * 2 * 64 * 16 * sizeof(uint4);   // 32 KB
    cudaFuncSetAttribute((const void*)gemm_mma<true, 3, true, false, false, true>,
                         cudaFuncAttributeMaxDynamicSharedMemorySize, (int)gsm3);
    cudaFuncSetAttribute((const void*)gemm_mma<false, 1, false, true, true, false>,
                         cudaFuncAttributeMaxDynamicSharedMemorySize, (int)ASZ);
    cudaFuncSetAttribute((const void*)attn2<16, 256>, cudaFuncAttributeMaxDynamicSharedMemorySize, (int)asm16);
    cudaFuncSetAttribute((const void*)attn2<64, 256>, cudaFuncAttributeMaxDynamicSharedMemorySize, (int)asm64);

    build_ws<<<(n16 + 255) / 256, 256>>>(fp16i, n16, 16, ws16, nw16);
    build_ws<<<(n64 + 255) / 256, 256>>>(fp64i, n64, 64, ws64, nw64);
    pack_w<<<64, 256>>>(Win, Wout);

    const int gt = (ntok + 63) / 64;
    const size_t off = (size_t)n16 * D;

    // Fused Q+K+V over BOTH groups: one gather, three matrices, fp16 outputs.
    gemm_mma<true, 3, true, false, false, true><<<gt, 256, gsm3>>>(
        feat, vox16, vox64, pos16, pos64, fp16i, fp64i, 0, bin,
        Qh, Kh, Vh, nullptr, nullptr, n16, ntok);

    // Attention (fp16 I/O): 2 queries/thread, chunked online softmax
    attn2<16, 256><<<(nw16 + 3) / 4, 256, asm16>>>(Qh, Kh, Vh, ws16, AO, nw16);
    attn2<64, 256><<<nw64, 256, asm64>>>(Qh + off, Kh + off, Vh + off, ws64, AO + off, nw64);

    // Output projection (fp16 in, fp32 out), scattered straight into d_out
    gemm_mma<false, 1, false, true, true, false><<<gt, 256, ASZ>>>(
        AO, nullptr, nullptr, nullptr, nullptr, nullptr, nullptr, 3, bout,
        out, nullptr, nullptr, vox16, vox64, n16, ntok);
}

// round 12
// speedup vs baseline: 4.4284x; 1.1888x over previous
#include <cuda_runtime.h>
#include <cuda_fp16.h>
#include <math.h>

#define D 128
#define NMAX 210048
#define SAH 68   // A-tile row stride in half2 words (272B); 68 % 32 == 4 -> conflict-free ldmatrix

// Scratch: Q, K, V, attention-out in fp16
__device__ float g_scr[(size_t)4 * NMAX * D / 2 + 1024];
__device__ uint2 g_wpackh[4 * 8 * 16 * 32];   // fp16 m16n8k16 B fragments, 32KB/matrix
__device__ int g_ws16[20002];
__device__ int g_ws64[8002];

__device__ __forceinline__ __half2 u2h(unsigned u) { return *(__half2*)&u; }

// ---------------------------------------------------------------------------
__global__ void build_ws(const int* __restrict__ fp, int n, int L,
                         int* __restrict__ ws, int nw)
{
    int i = blockIdx.x * blockDim.x + threadIdx.x;
    if (i < n) {
        int w = fp[i] / L;
        if (i == 0 || fp[i - 1] / L != w) ws[w] = i;
    }
    if (i == 0) ws[nw] = n;
}

// ---------------------------------------------------------------------------
// Pack W into m16n8k16 fp16 B-fragment order.
// ---------------------------------------------------------------------------
__global__ void pack_w(const float* __restrict__ Win, const float* __restrict__ Wout)
{
    int i = blockIdx.x * blockDim.x + threadIdx.x;   // 0..16383
    if (i >= 4 * 8 * 16 * 32) return;
    int lane = i & 31;
    int nf = (i >> 5) & 15;
    int ks = (i >> 9) & 7;
    int m  = i >> 12;
    int g = lane >> 2, t4 = lane & 3;
    const float* W = (m < 3) ? (Win + (size_t)m * D * D) : Wout;
    int n  = nf * 8 + g;
    int k0 = ks * 16 + 2 * t4;
    __half2 b0 = __floats2half2_rn(W[n * D + k0],     W[n * D + k0 + 1]);
    __half2 b1 = __floats2half2_rn(W[n * D + k0 + 8], W[n * D + k0 + 9]);
    uint2 out;
    out.x = *(unsigned*)&b0;
    out.y = *(unsigned*)&b1;
    g_wpackh[i] = out;
}

// ---------------------------------------------------------------------------
// FP16 tensor-core GEMM (m16n8k16, fp32 accum); A-frags via ldmatrix.x4.
// ---------------------------------------------------------------------------
template <bool ADD_POS, int NM, bool GATHER, bool SCATTER, bool HIN, bool HOUT>
__global__ __launch_bounds__(256, 4)
void gemm_mma(const void* __restrict__ Xv,
              const int* __restrict__ g16, const int* __restrict__ g64,
              const float* __restrict__ pos16, const float* __restrict__ pos64,
              const int* __restrict__ fp16x, const int* __restrict__ fp64x,
              int wmat, const float* __restrict__ bias,
              void* __restrict__ O0, void* __restrict__ O1, void* __restrict__ O2,
              const int* __restrict__ s16, const int* __restrict__ s64,
              int n16, int ntok)
{
    extern __shared__ unsigned smu[];                 // A tiles as half2 words
    unsigned* As = smu;                               // 64 x SAH  (pos-added / only)
    unsigned* Ar = (NM == 3) ? smu + 64 * SAH : smu;  // raw tile (V operand)
    const int tid = threadIdx.x;
    const int tb = blockIdx.x * 64;

    // Stage A
#pragma unroll
    for (int it = 0; it < 8; it++) {
        int idx = tid + it * 256;
        int r  = idx >> 5;
        int c4 = (idx & 31) << 2;
        int tk = tb + r;
        int wi = r * SAH + (c4 >> 1);
        if (HIN) {
            uint2 st = make_uint2(0u, 0u);
            if (tk < ntok) {
                const unsigned* Xh = (const unsigned*)Xv;
                st = *(const uint2*)(Xh + (size_t)tk * 64 + (c4 >> 1));
            }
            *(uint2*)(As + wi) = st;
        } else {
            const float* X = (const float*)Xv;
            float4 v = make_float4(0.f, 0.f, 0.f, 0.f);
            float4 vp = v;
            if (tk < ntok) {
                bool gA = tk < n16;
                int src = GATHER ? (gA ? g16[tk] : g64[tk - n16]) : tk;
                v = *(const float4*)(X + (size_t)src * D + c4);
                vp = v;
                if (ADD_POS) {
                    const float* P = gA ? pos16 : pos64;
                    int f = gA ? fp16x[tk] : fp64x[tk - n16];
                    float4 p = *(const float4*)(P + (size_t)f * D + c4);
                    vp.x += p.x; vp.y += p.y; vp.z += p.z; vp.w += p.w;
                }
            }
            {
                __half2 h0 = __floats2half2_rn(vp.x, vp.y);
                __half2 h1 = __floats2half2_rn(vp.z, vp.w);
                uint2 st; st.x = *(unsigned*)&h0; st.y = *(unsigned*)&h1;
                *(uint2*)(As + wi) = st;
            }
            if (NM == 3) {
                __half2 h0 = __floats2half2_rn(v.x, v.y);
                __half2 h1 = __floats2half2_rn(v.z, v.w);
                uint2 st; st.x = *(unsigned*)&h0; st.y = *(unsigned*)&h1;
                *(uint2*)(Ar + wi) = st;
            }
        }
    }
    __syncthreads();

    const int w  = tid >> 5, lane = tid & 31;
    const int wm = w & 1,  wn = w >> 1;
    const int g  = lane >> 2, t4 = lane & 3;

    // ldmatrix.x4 source address: lanes 0-7 rows 0-7 (k-lo), 8-15 rows 8-15 (k-lo),
    // 16-23 rows 0-7 (k-hi), 24-31 rows 8-15 (k-hi) -> frags a0..a3 in mma order.
    unsigned a_base;
    {
        int rowp = wm * 32 + (lane & 7) + ((lane >> 3) & 1) * 8;
        int colw = (lane >> 4) * 4;
        a_base = (unsigned)__cvta_generic_to_shared(As + rowp * SAH + colw);
    }

#pragma unroll
    for (int m = 0; m < NM; m++) {
        const unsigned ab = a_base + ((NM == 3 && m == 2) ? 64 * SAH * 4 : 0);
        float acc[2][4][4];
#pragma unroll
        for (int ma = 0; ma < 2; ma++)
#pragma unroll
            for (int nf = 0; nf < 4; nf++)
#pragma unroll
                for (int e = 0; e < 4; e++) acc[ma][nf][e] = 0.f;

        const uint2* bp = g_wpackh + ((size_t)(wmat + m) * 8 * 16 + wn * 4) * 32 + lane;

#pragma unroll
        for (int ks = 0; ks < 8; ks++) {
            unsigned a[2][4];
#pragma unroll
            for (int ma = 0; ma < 2; ma++) {
                asm volatile(
                    "ldmatrix.sync.aligned.m8n8.x4.shared.b16 {%0,%1,%2,%3}, [%4];"
                    : "=r"(a[ma][0]), "=r"(a[ma][1]), "=r"(a[ma][2]), "=r"(a[ma][3])
                    : "r"(ab + ma * 16 * SAH * 4 + ks * 32));
            }
#pragma unroll
            for (int nf = 0; nf < 4; nf++) {
                uint2 bv = __ldg(bp + (ks * 16 + nf) * 32);
#pragma unroll
                for (int ma = 0; ma < 2; ma++) {
                    asm volatile(
                        "mma.sync.aligned.m16n8k16.row.col.f32.f16.f16.f32 "
                        "{%0,%1,%2,%3}, {%4,%5,%6,%7}, {%8,%9}, {%0,%1,%2,%3};"
                        : "+f"(acc[ma][nf][0]), "+f"(acc[ma][nf][1]),
                          "+f"(acc[ma][nf][2]), "+f"(acc[ma][nf][3])
                        : "r"(a[ma][0]), "r"(a[ma][1]), "r"(a[ma][2]), "r"(a[ma][3]),
                          "r"(bv.x), "r"(bv.y));
                }
            }
        }

        const float* bm = bias + m * D;
        void* OUT = (m == 0) ? O0 : (m == 1) ? O1 : O2;
#pragma unroll
        for (int ma = 0; ma < 2; ma++) {
#pragma unroll
            for (int rr = 0; rr < 2; rr++) {
                int r = tb + wm * 32 + ma * 16 + g + rr * 8;
                if (r < ntok) {
                    int rowg = r;
                    if (SCATTER) rowg = (r < n16) ? s16[r] : s64[r - n16];
#pragma unroll
                    for (int nf = 0; nf < 4; nf++) {
                        int c = wn * 32 + nf * 8 + 2 * t4;
                        float2 bi = *(const float2*)(bm + c);
                        float vx = acc[ma][nf][rr * 2 + 0] + bi.x;
                        float vy = acc[ma][nf][rr * 2 + 1] + bi.y;
                        if (HOUT) {
                            __half* o = (__half*)OUT + (size_t)rowg * D;
                            *(__half2*)(o + c) = __floats2half2_rn(vx, vy);
                        } else {
                            float* o = (float*)OUT + (size_t)rowg * D;
                            *(float2*)(o + c) = make_float2(vx, vy);
                        }
                    }
                }
            }
        }
    }
}

// ---------------------------------------------------------------------------
__device__ __forceinline__ void h8_to_f(const uint4& u, float* f) {
    float2 a = __half22float2(*(const __half2*)&u.x); f[0] = a.x; f[1] = a.y;
    float2 b = __half22float2(*(const __half2*)&u.y); f[2] = b.x; f[3] = b.y;
    float2 c = __half22float2(*(const __half2*)&u.z); f[4] = c.x; f[5] = c.y;
    float2 d = __half22float2(*(const __half2*)&u.w); f[6] = d.x; f[7] = d.y;
}

// fp16 dot of 16 halves (two uint4 pairs), fp32 result
__device__ __forceinline__ float dot16h(const uint4& qa, const uint4& qb,
                                        const uint4& ka, const uint4& kb) {
    __half2 t = __hmul2(u2h(qa.x), u2h(ka.x));
    t = __hfma2(u2h(qa.y), u2h(ka.y), t);
    t = __hfma2(u2h(qa.z), u2h(ka.z), t);
    t = __hfma2(u2h(qa.w), u2h(ka.w), t);
    __half2 s = __hmul2(u2h(qb.x), u2h(kb.x));
    s = __hfma2(u2h(qb.y), u2h(kb.y), s);
    s = __hfma2(u2h(qb.z), u2h(kb.z), s);
    s = __hfma2(u2h(qb.w), u2h(kb.w), s);
    float2 f = __half22float2(__hadd2(t, s));
    return f.x + f.y;
}

// ---------------------------------------------------------------------------
// s16 attention: 2 queries/thread.
// ---------------------------------------------------------------------------
template <int L, int TPB>
__global__ __launch_bounds__(TPB)
void attn2(const __half* __restrict__ Q, const __half* __restrict__ K,
           const __half* __restrict__ V, const int* __restrict__ ws,
           __half* __restrict__ AO, int nw)
{
    constexpr int QS  = L / 2;
    constexpr int TPW = QS * 8;
    constexpr int WPB = TPB / TPW;
    extern __shared__ uint4 smh[];
    const int tid = threadIdx.x;
    const int wl  = tid / TPW;
    const int w   = blockIdx.x * WPB + wl;
    uint4* Ks = smh + (size_t)wl * (2 * L * 16);
    uint4* Vs = Ks + L * 16;

    int t0 = 0, len = 0;
    if (w < nw) { t0 = ws[w]; len = ws[w + 1] - t0; }

    const int lt = tid - wl * TPW;
    for (int idx = lt; idx < len * 16; idx += TPW) {
        int j = idx >> 4, gg = idx & 15;
        int h = gg >> 1, p = gg & 1;
        Ks[j * 16 + (p * 8 + h)] = ((const uint4*)K)[(size_t)(t0 + j) * 16 + gg];
        Vs[j * 16 + (p * 8 + h)] = ((const uint4*)V)[(size_t)(t0 + j) * 16 + gg];
    }
    __syncthreads();

    const int qs = lt >> 3;
    const int h  = lt & 7;
    const int q0 = 2 * qs, q1 = 2 * qs + 1;
    if (w >= nw || q0 >= len) return;
    const bool v1 = (q1 < len);

    uint4 qa0, qb0, qa1, qb1;
    {
        const uint4* Qp0 = (const uint4*)Q + (size_t)(t0 + q0) * 16 + h * 2;
        const uint4* Qp1 = (const uint4*)Q + (size_t)(t0 + (v1 ? q1 : q0)) * 16 + h * 2;
        qa0 = Qp0[0]; qb0 = Qp0[1];
        qa1 = Qp1[0]; qb1 = Qp1[1];
    }

    float s0[L], s1[L];
    float m0 = -1e30f, m1 = -1e30f;
#pragma unroll
    for (int j = 0; j < L; j++) {
        bool kv = j < len;
        int key = kv ? j : 0;
        uint4 ka = Ks[key * 16 + h], kb = Ks[key * 16 + 8 + h];
        float a = dot16h(qa0, qb0, ka, kb);
        float b = dot16h(qa1, qb1, ka, kb);
        s0[j] = kv ? a : -1e30f;
        s1[j] = kv ? b : -1e30f;
        m0 = fmaxf(m0, s0[j]); m1 = fmaxf(m1, s1[j]);
    }
    float d0 = 0.f, d1 = 0.f;
    float acc0[16], acc1[16];
#pragma unroll
    for (int e = 0; e < 16; e++) { acc0[e] = 0.f; acc1[e] = 0.f; }
#pragma unroll
    for (int j = 0; j < L; j++) {
        if (j >= len) break;
        float p0 = __expf((s0[j] - m0) * 0.25f);
        float p1 = __expf((s1[j] - m1) * 0.25f);
        d0 += p0; d1 += p1;
        float vf[16];
        h8_to_f(Vs[j * 16 + h], vf); h8_to_f(Vs[j * 16 + 8 + h], vf + 8);
#pragma unroll
        for (int e = 0; e < 16; e++) {
            acc0[e] += p0 * vf[e];
            acc1[e] += p1 * vf[e];
        }
    }
    {
        float inv = 1.f / d0;
        __half2* o = (__half2*)(AO + (size_t)(t0 + q0) * D + h * 16);
#pragma unroll
        for (int e = 0; e < 8; e++)
            o[e] = __floats2half2_rn(acc0[2 * e] * inv, acc0[2 * e + 1] * inv);
    }
    if (v1) {
        float inv = 1.f / d1;
        __half2* o = (__half2*)(AO + (size_t)(t0 + q1) * D + h * 16);
#pragma unroll
        for (int e = 0; e < 8; e++)
            o[e] = __floats2half2_rn(acc1[2 * e] * inv, acc1[2 * e + 1] * inv);
    }
}

// ---------------------------------------------------------------------------
// s64 attention: 4 queries/thread, 8-key chunked online softmax, fp16 QK dot,
// fp32 PV accumulation. 1 window/block, 128 threads.
// ---------------------------------------------------------------------------
__global__ __launch_bounds__(128)
void attn4(const __half* __restrict__ Q, const __half* __restrict__ K,
           const __half* __restrict__ V, const int* __restrict__ ws,
           __half* __restrict__ AO, int nw)
{
    constexpr int L = 64;
    __shared__ uint4 smkv[2 * L * 16];   // 32 KB
    uint4* Ks = smkv;
    uint4* Vs = smkv + L * 16;
    const int w = blockIdx.x;
    const int t0 = ws[w];
    const int len = ws[w + 1] - t0;
    const int tid = threadIdx.x;

    for (int idx = tid; idx < len * 16; idx += 128) {
        int j = idx >> 4, gg = idx & 15;
        int h = gg >> 1, p = gg & 1;
        Ks[j * 16 + (p * 8 + h)] = ((const uint4*)K)[(size_t)(t0 + j) * 16 + gg];
        Vs[j * 16 + (p * 8 + h)] = ((const uint4*)V)[(size_t)(t0 + j) * 16 + gg];
    }
    __syncthreads();

    const int qs = tid >> 3;
    const int h  = tid & 7;
    const int q0 = 4 * qs;
    if (q0 >= len) return;
    const int nq = min(4, len - q0);

    uint4 qa[4], qb[4];
#pragma unroll
    for (int qi = 0; qi < 4; qi++) {
        int qq = q0 + (qi < nq ? qi : nq - 1);
        const uint4* Qp = (const uint4*)Q + (size_t)(t0 + qq) * 16 + h * 2;
        qa[qi] = Qp[0]; qb[qi] = Qp[1];
    }

    float m[4], d[4], acc[4][16];
#pragma unroll
    for (int qi = 0; qi < 4; qi++) {
        m[qi] = -1e30f; d[qi] = 0.f;
#pragma unroll
        for (int e = 0; e < 16; e++) acc[qi][e] = 0.f;
    }

    for (int c0 = 0; c0 < len; c0 += 8) {
        float s[4][8];
#pragma unroll
        for (int j = 0; j < 8; j++) {
            bool kv = (c0 + j) < len;
            int key = kv ? c0 + j : 0;
            uint4 ka = Ks[key * 16 + h], kb = Ks[key * 16 + 8 + h];
#pragma unroll
            for (int qi = 0; qi < 4; qi++)
                s[qi][j] = kv ? dot16h(qa[qi], qb[qi], ka, kb) : -1e30f;
        }
#pragma unroll
        for (int qi = 0; qi < 4; qi++) {
            float cm = s[qi][0];
#pragma unroll
            for (int j = 1; j < 8; j++) cm = fmaxf(cm, s[qi][j]);
            float mn = fmaxf(m[qi], cm);
            float sc = __expf((m[qi] - mn) * 0.25f);
            m[qi] = mn;
            d[qi] *= sc;
#pragma unroll
            for (int e = 0; e < 16; e++) acc[qi][e] *= sc;
        }
#pragma unroll
        for (int j = 0; j < 8; j++) {
            if (c0 + j >= len) break;
            float vf[16];
            h8_to_f(Vs[(c0 + j) * 16 + h], vf);
            h8_to_f(Vs[(c0 + j) * 16 + 8 + h], vf + 8);
            float p[4];
#pragma unroll
            for (int qi = 0; qi < 4; qi++) {
                p[qi] = __expf((s[qi][j] - m[qi]) * 0.25f);
                d[qi] += p[qi];
            }
#pragma unroll
            for (int e = 0; e < 16; e++) {
#pragma unroll
                for (int qi = 0; qi < 4; qi++)
                    acc[qi][e] += p[qi] * vf[e];
            }
        }
    }

#pragma unroll
    for (int qi = 0; qi < 4; qi++) {
        if (qi >= nq) break;
        float inv = 1.f / d[qi];
        __half2* o = (__half2*)(AO + (size_t)(t0 + q0 + qi) * D + h * 16);
#pragma unroll
        for (int e = 0; e < 8; e++)
            o[e] = __floats2half2_rn(acc[qi][2 * e] * inv, acc[qi][2 * e + 1] * inv);
    }
}

// ---------------------------------------------------------------------------
extern "C" void kernel_launch(void* const* d_in, const int* in_sizes, int n_in,
                              void* d_out, int out_size)
{
    const float* feat  = (const float*)d_in[0];
    const float* pos16 = (const float*)d_in[1];
    const float* pos64 = (const float*)d_in[2];
    const float* Win   = (const float*)d_in[3];
    const float* bin   = (const float*)d_in[4];
    const float* Wout  = (const float*)d_in[5];
    const float* bout  = (const float*)d_in[6];
    const int* vox16 = (const int*)d_in[7];
    const int* fp16i = (const int*)d_in[8];
    const int* vox64 = (const int*)d_in[9];
    const int* fp64i = (const int*)d_in[10];
    const int n16  = in_sizes[7];
    const int n64  = in_sizes[9];
    const int nw16 = in_sizes[1] / (16 * D);
    const int nw64 = in_sizes[2] / (64 * D);
    const int ntok = n16 + n64;
    float* out = (float*)d_out;

    float* scr = nullptr;
    cudaGetSymbolAddress((void**)&scr, g_scr);
    int* ws16 = nullptr; cudaGetSymbolAddress((void**)&ws16, g_ws16);
    int* ws64 = nullptr; cudaGetSymbolAddress((void**)&ws64, g_ws64);
    __half* Qh = (__half*)scr;
    __half* Kh = Qh + (size_t)NMAX * D;
    __half* Vh = Qh + (size_t)2 * NMAX * D;
    __half* AO = Qh + (size_t)3 * NMAX * D;

    const size_t ASZ   = (size_t)64 * SAH * sizeof(unsigned);       // 17408
    const size_t gsm3  = 2 * ASZ;                                   // 34816 (QKV)
    const size_t asm16 = (size_t)4 * 2 * 16 * 16 * sizeof(uint4);   // 32 KB
    cudaFuncSetAttribute((const void*)gemm_mma<true, 3, true, false, false, true>,
                         cudaFuncAttributeMaxDynamicSharedMemorySize, (int)gsm3);
    cudaFuncSetAttribute((const void*)gemm_mma<false, 1, false, true, true, false>,
                         cudaFuncAttributeMaxDynamicSharedMemorySize, (int)ASZ);
    cudaFuncSetAttribute((const void*)attn2<16, 256>, cudaFuncAttributeMaxDynamicSharedMemorySize, (int)asm16);

    build_ws<<<(n16 + 255) / 256, 256>>>(fp16i, n16, 16, ws16, nw16);
    build_ws<<<(n64 + 255) / 256, 256>>>(fp64i, n64, 64, ws64, nw64);
    pack_w<<<64, 256>>>(Win, Wout);

    const int gt = (ntok + 63) / 64;
    const size_t off = (size_t)n16 * D;

    // Fused Q+K+V over BOTH groups: one gather, three matrices, fp16 outputs.
    gemm_mma<true, 3, true, false, false, true><<<gt, 256, gsm3>>>(
        feat, vox16, vox64, pos16, pos64, fp16i, fp64i, 0, bin,
        Qh, Kh, Vh, nullptr, nullptr, n16, ntok);

    // Attention
    attn2<16, 256><<<(nw16 + 3) / 4, 256, asm16>>>(Qh, Kh, Vh, ws16, AO, nw16);
    attn4<<<nw64, 128>>>(Qh + off, Kh + off, Vh + off, ws64, AO + off, nw64);

    // Output projection (fp16 in, fp32 out), scattered straight into d_out
    gemm_mma<false, 1, false, true, true, false><<<gt, 256, ASZ>>>(
        AO, nullptr, nullptr, nullptr, nullptr, nullptr, nullptr, 3, bout,
        out, nullptr, nullptr, vox16, vox64, n16, ntok);
}